// round 1
// baseline (speedup 1.0000x reference)
#include <cuda_runtime.h>

#define BB 8
#define TT 4096
#define DD 512
#define HH 64

// Scratch for projected q, k, v: 3 x 8MB (device globals: allocation-free)
__device__ float g_q[BB * TT * HH];
__device__ float g_k[BB * TT * HH];
__device__ float g_v[BB * TT * HH];

// ---------------------------------------------------------------------------
// Kernel 1: QKV projection.  out[m][h] = sum_d x[m][d] * W[d][h] for 3 W's.
// Grid: 512 CTAs x 256 threads. Each CTA: 64 rows x (3 x 64) cols.
// K chunked by 32 (keeps static smem under 48KB).
// ---------------------------------------------------------------------------
__global__ __launch_bounds__(256) void proj_kernel(
    const float* __restrict__ x,
    const float* __restrict__ Wq,
    const float* __restrict__ Wk,
    const float* __restrict__ Wv)
{
    __shared__ float Xs[64][36];        // 64 rows x 32 k (pad 36, keeps f4 align)
    __shared__ float Ws[3][32][64];     // per-matrix 32 k x 64 h chunk

    const int tid  = threadIdx.x;
    const int row0 = blockIdx.x * 64;
    const int ty   = tid >> 4;   // 0..15 -> 4 rows each
    const int tx   = tid & 15;   // 0..15 -> 4 cols each (per matrix)

    float4 acc[4][3];
    #pragma unroll
    for (int i = 0; i < 4; i++)
        #pragma unroll
        for (int m = 0; m < 3; m++)
            acc[i][m] = make_float4(0.f, 0.f, 0.f, 0.f);

    const float* Wm0 = Wq;
    const float* Wm1 = Wk;
    const float* Wm2 = Wv;

    for (int k0 = 0; k0 < DD; k0 += 32) {
        // ---- load X chunk: 64 rows x 32 cols (512 float4) ----
        {
            int r  = tid >> 3;         // 0..31
            int c4 = (tid & 7) * 4;    // 0,4,...,28
            #pragma unroll
            for (int it = 0; it < 2; it++) {
                int rr = r + it * 32;
                float4 xv = *(const float4*)&x[(size_t)(row0 + rr) * DD + k0 + c4];
                *(float4*)&Xs[rr][c4] = xv;
            }
        }
        // ---- load W chunks: 3 x (32 x 64) = 3 x 512 float4 ----
        {
            #pragma unroll
            for (int it = 0; it < 2; it++) {
                int idx = tid + it * 256;   // float4 index 0..511
                float4 w0 = *(const float4*)&Wm0[(size_t)k0 * HH + idx * 4];
                float4 w1 = *(const float4*)&Wm1[(size_t)k0 * HH + idx * 4];
                float4 w2 = *(const float4*)&Wm2[(size_t)k0 * HH + idx * 4];
                *(float4*)&Ws[0][0][idx * 4] = w0;
                *(float4*)&Ws[1][0][idx * 4] = w1;
                *(float4*)&Ws[2][0][idx * 4] = w2;
            }
        }
        __syncthreads();

        #pragma unroll 8
        for (int kk = 0; kk < 32; kk++) {
            float xr[4];
            #pragma unroll
            for (int i = 0; i < 4; i++) xr[i] = Xs[ty * 4 + i][kk];
            #pragma unroll
            for (int m = 0; m < 3; m++) {
                float4 wv = *(float4*)&Ws[m][kk][tx * 4];
                #pragma unroll
                for (int i = 0; i < 4; i++) {
                    acc[i][m].x = fmaf(xr[i], wv.x, acc[i][m].x);
                    acc[i][m].y = fmaf(xr[i], wv.y, acc[i][m].y);
                    acc[i][m].z = fmaf(xr[i], wv.z, acc[i][m].z);
                    acc[i][m].w = fmaf(xr[i], wv.w, acc[i][m].w);
                }
            }
        }
        __syncthreads();
    }

    #pragma unroll
    for (int i = 0; i < 4; i++) {
        size_t row = (size_t)(row0 + ty * 4 + i);
        *(float4*)&g_q[row * HH + tx * 4] = acc[i][0];
        *(float4*)&g_k[row * HH + tx * 4] = acc[i][1];
        *(float4*)&g_v[row * HH + tx * 4] = acc[i][2];
    }
}

// ---------------------------------------------------------------------------
// Kernel 2: flash-style causal attention (fp32, online softmax).
// CTA: 128 threads (4 warps), 16 queries (4 per warp). Key tiles of 64.
// Lane owns 2 keys (scores) and 2 output dims (PV accumulation).
// ---------------------------------------------------------------------------
__global__ __launch_bounds__(128) void flash_kernel(float* __restrict__ out)
{
    __shared__ float k_t[HH][66];      // transposed K tile [h][j], pad 66
    __shared__ float v_s[64][HH];      // V tile [j][h]
    __shared__ float q_s[16][HH];      // Q tile [qi][h]
    __shared__ float p_s[4][4][64];    // probabilities [warp][q][j]

    const int b    = blockIdx.y;
    const int i0   = (gridDim.x - 1 - blockIdx.x) * 16;  // big workloads first
    const int tid  = threadIdx.x;
    const int warp = tid >> 5;
    const int lane = tid & 31;

    const float* qg = g_q + (size_t)b * TT * HH;
    const float* kg = g_k + (size_t)b * TT * HH;
    const float* vg = g_v + (size_t)b * TT * HH;

    // load Q tile (16 x 64 = 256 float4)
    for (int idx = tid; idx < 256; idx += 128) {
        int r  = idx >> 4;
        int c4 = (idx & 15) * 4;
        *(float4*)&q_s[r][c4] = *(const float4*)&qg[(size_t)(i0 + r) * HH + c4];
    }

    float m[4], l[4], acc0[4], acc1[4];
    #pragma unroll
    for (int q = 0; q < 4; q++) { m[q] = -1e30f; l[q] = 0.f; acc0[q] = 0.f; acc1[q] = 0.f; }

    const float scale = 0.04419417382415922f;  // 512^-0.5
    const int ntiles = i0 / 64 + 1;

    for (int t = 0; t < ntiles; t++) {
        const int j0 = t * 64;
        __syncthreads();   // previous tile fully consumed (also orders q_s on t==0)

        // ---- load K (transposed) and V tiles ----
        #pragma unroll
        for (int it = 0; it < 8; it++) {
            int jj = (tid >> 4) + it * 8;       // 0..63
            int h4 = (tid & 15) * 4;            // 0..60
            float4 kv4 = *(const float4*)&kg[(size_t)(j0 + jj) * HH + h4];
            k_t[h4 + 0][jj] = kv4.x;
            k_t[h4 + 1][jj] = kv4.y;
            k_t[h4 + 2][jj] = kv4.z;
            k_t[h4 + 3][jj] = kv4.w;
            float4 vv4 = *(const float4*)&vg[(size_t)(j0 + jj) * HH + h4];
            *(float4*)&v_s[jj][h4] = vv4;
        }
        __syncthreads();

        // ---- S = Q K^T (lane keys: j = j0 + 2*lane, +1) ----
        float s0[4] = {0.f, 0.f, 0.f, 0.f};
        float s1[4] = {0.f, 0.f, 0.f, 0.f};
        #pragma unroll 8
        for (int h = 0; h < HH; h += 2) {
            float2 ka = *(float2*)&k_t[h][lane * 2];
            float2 kb = *(float2*)&k_t[h + 1][lane * 2];
            #pragma unroll
            for (int q = 0; q < 4; q++) {
                float2 qh = *(float2*)&q_s[warp * 4 + q][h];
                s0[q] = fmaf(qh.x, ka.x, s0[q]);
                s0[q] = fmaf(qh.y, kb.x, s0[q]);
                s1[q] = fmaf(qh.x, ka.y, s1[q]);
                s1[q] = fmaf(qh.y, kb.y, s1[q]);
            }
        }

        // ---- mask, online softmax update, stage P ----
        const int jg0 = j0 + lane * 2;
        #pragma unroll
        for (int q = 0; q < 4; q++) {
            const int iq = i0 + warp * 4 + q;
            float a  = (jg0     <= iq) ? s0[q] * scale : -1e30f;
            float bq = (jg0 + 1 <= iq) ? s1[q] * scale : -1e30f;
            float tm = fmaxf(a, bq);
            #pragma unroll
            for (int o = 16; o > 0; o >>= 1)
                tm = fmaxf(tm, __shfl_xor_sync(0xffffffffu, tm, o));
            float mn   = fmaxf(m[q], tm);
            float corr = __expf(m[q] - mn);
            float p0   = __expf(a - mn);
            float p1   = __expf(bq - mn);
            float ps   = p0 + p1;
            #pragma unroll
            for (int o = 16; o > 0; o >>= 1)
                ps += __shfl_xor_sync(0xffffffffu, ps, o);
            l[q]    = l[q] * corr + ps;
            m[q]    = mn;
            acc0[q] *= corr;
            acc1[q] *= corr;
            *(float2*)&p_s[warp][q][lane * 2] = make_float2(p0, p1);
        }
        __syncwarp();

        // ---- O += P V (lane dims: h = 2*lane, +1) ----
        #pragma unroll 8
        for (int j = 0; j < 64; j += 2) {
            float2 va = *(float2*)&v_s[j][lane * 2];
            float2 vb = *(float2*)&v_s[j + 1][lane * 2];
            #pragma unroll
            for (int q = 0; q < 4; q++) {
                float2 pp = *(float2*)&p_s[warp][q][j];
                acc0[q] = fmaf(pp.x, va.x, acc0[q]);
                acc0[q] = fmaf(pp.y, vb.x, acc0[q]);
                acc1[q] = fmaf(pp.x, va.y, acc1[q]);
                acc1[q] = fmaf(pp.y, vb.y, acc1[q]);
            }
        }
    }

    // ---- epilogue: O / l ----
    #pragma unroll
    for (int q = 0; q < 4; q++) {
        const int iq = i0 + warp * 4 + q;
        float inv = 1.0f / l[q];
        *(float2*)&out[((size_t)b * TT + iq) * HH + lane * 2] =
            make_float2(acc0[q] * inv, acc1[q] * inv);
    }
}

// ---------------------------------------------------------------------------
extern "C" void kernel_launch(void* const* d_in, const int* in_sizes, int n_in,
                              void* d_out, int out_size)
{
    (void)in_sizes; (void)n_in; (void)out_size;
    const float* x  = (const float*)d_in[0];
    const float* Wq = (const float*)d_in[1];
    const float* Wk = (const float*)d_in[2];
    const float* Wv = (const float*)d_in[3];
    float* out = (float*)d_out;

    proj_kernel<<<(BB * TT) / 64, 256>>>(x, Wq, Wk, Wv);
    flash_kernel<<<dim3(TT / 16, BB), 128>>>(out);
}

// round 3
// speedup vs baseline: 3.4611x; 3.4611x over previous
#include <cuda_runtime.h>
#include <cuda_fp16.h>
#include <cstdint>

#define BB 8
#define TT 4096
#define DD 512
#define HH 64

// fp16 projected tensors (device globals: allocation-free)
__device__ __half g_qh[BB * TT * HH];           // [b*T + t][h]
__device__ __half g_kh[BB * TT * HH];           // [b*T + t][h]
__device__ __half g_vt[BB * HH * TT];           // [b][h][t]  (V transposed)

__device__ __forceinline__ uint32_t smem_to_u32(const void* p) {
    uint32_t a;
    asm("{ .reg .u64 t; cvta.to.shared.u64 t, %1; cvt.u32.u64 %0, t; }" : "=r"(a) : "l"(p));
    return a;
}

// ---------------------------------------------------------------------------
// Kernel 1: QKV projection (fp32 compute, fp16 outputs; V written transposed)
// ---------------------------------------------------------------------------
__global__ __launch_bounds__(256) void proj_kernel(
    const float* __restrict__ x,
    const float* __restrict__ Wq,
    const float* __restrict__ Wk,
    const float* __restrict__ Wv)
{
    __shared__ float Xs[64][36];
    __shared__ float Ws[3][32][64];

    const int tid  = threadIdx.x;
    const int row0 = blockIdx.x * 64;
    const int ty   = tid >> 4;
    const int tx   = tid & 15;

    float4 acc[4][3];
    #pragma unroll
    for (int i = 0; i < 4; i++)
        #pragma unroll
        for (int m = 0; m < 3; m++)
            acc[i][m] = make_float4(0.f, 0.f, 0.f, 0.f);

    for (int k0 = 0; k0 < DD; k0 += 32) {
        {
            int r  = tid >> 3;
            int c4 = (tid & 7) * 4;
            #pragma unroll
            for (int it = 0; it < 2; it++) {
                int rr = r + it * 32;
                *(float4*)&Xs[rr][c4] =
                    *(const float4*)&x[(size_t)(row0 + rr) * DD + k0 + c4];
            }
        }
        {
            #pragma unroll
            for (int it = 0; it < 2; it++) {
                int idx = tid + it * 256;
                float4 w0 = *(const float4*)&Wq[(size_t)k0 * HH + idx * 4];
                float4 w1 = *(const float4*)&Wk[(size_t)k0 * HH + idx * 4];
                float4 w2 = *(const float4*)&Wv[(size_t)k0 * HH + idx * 4];
                *(float4*)&Ws[0][0][idx * 4] = w0;
                *(float4*)&Ws[1][0][idx * 4] = w1;
                *(float4*)&Ws[2][0][idx * 4] = w2;
            }
        }
        __syncthreads();

        #pragma unroll 8
        for (int kk = 0; kk < 32; kk++) {
            float xr[4];
            #pragma unroll
            for (int i = 0; i < 4; i++) xr[i] = Xs[ty * 4 + i][kk];
            #pragma unroll
            for (int m = 0; m < 3; m++) {
                float4 wv = *(float4*)&Ws[m][kk][tx * 4];
                #pragma unroll
                for (int i = 0; i < 4; i++) {
                    acc[i][m].x = fmaf(xr[i], wv.x, acc[i][m].x);
                    acc[i][m].y = fmaf(xr[i], wv.y, acc[i][m].y);
                    acc[i][m].z = fmaf(xr[i], wv.z, acc[i][m].z);
                    acc[i][m].w = fmaf(xr[i], wv.w, acc[i][m].w);
                }
            }
        }
        __syncthreads();
    }

    #pragma unroll
    for (int i = 0; i < 4; i++) {
        const int row = row0 + ty * 4 + i;
        __half2 q01 = __floats2half2_rn(acc[i][0].x, acc[i][0].y);
        __half2 q23 = __floats2half2_rn(acc[i][0].z, acc[i][0].w);
        __half2 k01 = __floats2half2_rn(acc[i][1].x, acc[i][1].y);
        __half2 k23 = __floats2half2_rn(acc[i][1].z, acc[i][1].w);
        *(__half2*)&g_qh[(size_t)row * HH + tx * 4]     = q01;
        *(__half2*)&g_qh[(size_t)row * HH + tx * 4 + 2] = q23;
        *(__half2*)&g_kh[(size_t)row * HH + tx * 4]     = k01;
        *(__half2*)&g_kh[(size_t)row * HH + tx * 4 + 2] = k23;
        const int b  = row >> 12;
        const int tr = row & (TT - 1);
        const size_t vb = (size_t)b * HH * TT + tr;
        g_vt[vb + (size_t)(tx * 4 + 0) * TT] = __float2half(acc[i][2].x);
        g_vt[vb + (size_t)(tx * 4 + 1) * TT] = __float2half(acc[i][2].y);
        g_vt[vb + (size_t)(tx * 4 + 2) * TT] = __float2half(acc[i][2].z);
        g_vt[vb + (size_t)(tx * 4 + 3) * TT] = __float2half(acc[i][2].w);
    }
}

// ---------------------------------------------------------------------------
// Kernel 2: flash attention via mma.sync (HMMA) + ldmatrix, fp32 accumulate.
// CTA: 256 threads / 8 warps, 128 q rows (16 per warp). Key tiles of 64.
// P never round-trips through SMEM: S C-frags -> fp16 A-frags in registers.
// ---------------------------------------------------------------------------
#define PITCH 72   // halves per SMEM row (144B: 4-bank shift/row -> conflict-free ldmatrix)

__global__ __launch_bounds__(256, 2) void flash_mma(float* __restrict__ out)
{
    __shared__ __half Qs[128][PITCH];
    __shared__ __half Ks[64][PITCH];
    __shared__ __half Vs[64][PITCH];   // V^T tile: rows = h, cols = j

    const int tid  = threadIdx.x;
    const int warp = tid >> 5;
    const int lane = tid & 31;
    const int b    = blockIdx.y;
    const int qi0  = (int)(gridDim.x - 1 - blockIdx.x) * 128;  // biggest first

    const uint32_t qbase = smem_to_u32(Qs);
    const uint32_t kbase = smem_to_u32(Ks);
    const uint32_t vbase = smem_to_u32(Vs);

    const __half* qg  = g_qh + ((size_t)b * TT + qi0) * HH;
    const __half* kg  = g_kh + (size_t)b * TT * HH;
    const __half* vtg = g_vt + (size_t)b * HH * TT;

    // ---- load Q tile: 128 rows x 64 halves = 1024 uint4 ----
    #pragma unroll
    for (int it = 0; it < 4; ++it) {
        int idx = tid + it * 256;
        int r = idx >> 3, c = idx & 7;
        *(uint4*)&Qs[r][c * 8] = *(const uint4*)(qg + (size_t)r * HH + c * 8);
    }
    __syncthreads();

    // ---- Q A-fragments (held in registers for the whole kernel) ----
    const int mrow = warp * 16;
    uint32_t aq[4][4];
    {
        int row = mrow + (lane & 7) + ((lane >> 3) & 1) * 8;
        int col = ((lane >> 4) << 3);
        #pragma unroll
        for (int ks = 0; ks < 4; ++ks) {
            uint32_t ad = qbase + (uint32_t)(row * PITCH + ks * 16 + col) * 2;
            asm volatile("ldmatrix.sync.aligned.m8n8.x4.shared.b16 {%0,%1,%2,%3}, [%4];"
                : "=r"(aq[ks][0]), "=r"(aq[ks][1]), "=r"(aq[ks][2]), "=r"(aq[ks][3])
                : "r"(ad));
        }
    }

    const int r0  = qi0 + mrow + (lane >> 2);
    const int r1  = r0 + 8;
    const int cql = (lane & 3) * 2;

    float o[8][4];
    #pragma unroll
    for (int n = 0; n < 8; ++n)
        #pragma unroll
        for (int i = 0; i < 4; ++i) o[n][i] = 0.f;
    float l0 = 0.f, l1 = 0.f;

    // B-frag ldmatrix address components (same pattern for K and V)
    const int brow = lane & 7;
    const int bcol = lane & 8;
    const float scale = 0.044194173824159216f;   // 512^-0.5

    const int ntiles = qi0 / 64 + 2;

    for (int t = 0; t < ntiles; ++t) {
        const int j0 = t * 64;
        __syncthreads();   // previous tile fully consumed

        // ---- load K tile [64 j][64 h] and V^T tile [64 h][64 j] ----
        #pragma unroll
        for (int it = 0; it < 2; ++it) {
            int idx = tid + it * 256;
            int r = idx >> 3, c = idx & 7;
            *(uint4*)&Ks[r][c * 8] = *(const uint4*)(kg + (size_t)(j0 + r) * HH + c * 8);
            *(uint4*)&Vs[r][c * 8] = *(const uint4*)(vtg + (size_t)r * TT + j0 + c * 8);
        }
        __syncthreads();

        // ---- S = Q K^T : 8 j-tiles x 4 h-steps ----
        float s[8][4];
        #pragma unroll
        for (int n = 0; n < 8; ++n) {
            s[n][0] = s[n][1] = s[n][2] = s[n][3] = 0.f;
            #pragma unroll
            for (int ks = 0; ks < 4; ++ks) {
                uint32_t b0, b1;
                uint32_t ad = kbase + (uint32_t)((n * 8 + brow) * PITCH + ks * 16 + bcol) * 2;
                asm volatile("ldmatrix.sync.aligned.m8n8.x2.shared.b16 {%0,%1}, [%2];"
                    : "=r"(b0), "=r"(b1) : "r"(ad));
                asm volatile("mma.sync.aligned.m16n8k16.row.col.f32.f16.f16.f32 "
                    "{%0,%1,%2,%3}, {%4,%5,%6,%7}, {%8,%9}, {%0,%1,%2,%3};"
                    : "+f"(s[n][0]), "+f"(s[n][1]), "+f"(s[n][2]), "+f"(s[n][3])
                    : "r"(aq[ks][0]), "r"(aq[ks][1]), "r"(aq[ks][2]), "r"(aq[ks][3]),
                      "r"(b0), "r"(b1));
            }
        }

        // ---- exp + causal mask + pack P into A-fragment registers ----
        uint32_t pl[8], pr[8];
        #pragma unroll
        for (int n = 0; n < 8; ++n) {
            const int cb = j0 + n * 8 + cql;
            float e0 = __expf(s[n][0] * scale); if (cb     > r0) e0 = 0.f;
            float e1 = __expf(s[n][1] * scale); if (cb + 1 > r0) e1 = 0.f;
            float e2 = __expf(s[n][2] * scale); if (cb     > r1) e2 = 0.f;
            float e3 = __expf(s[n][3] * scale); if (cb + 1 > r1) e3 = 0.f;
            l0 += e0 + e1;
            l1 += e2 + e3;
            asm("cvt.rn.f16x2.f32 %0, %1, %2;" : "=r"(pl[n]) : "f"(e1), "f"(e0));
            asm("cvt.rn.f16x2.f32 %0, %1, %2;" : "=r"(pr[n]) : "f"(e3), "f"(e2));
        }

        // ---- O += P V : 8 h-tiles x 4 j-steps ----
        #pragma unroll
        for (int hn = 0; hn < 8; ++hn) {
            #pragma unroll
            for (int kk = 0; kk < 4; ++kk) {
                uint32_t b0, b1;
                uint32_t ad = vbase + (uint32_t)((hn * 8 + brow) * PITCH + kk * 16 + bcol) * 2;
                asm volatile("ldmatrix.sync.aligned.m8n8.x2.shared.b16 {%0,%1}, [%2];"
                    : "=r"(b0), "=r"(b1) : "r"(ad));
                asm volatile("mma.sync.aligned.m16n8k16.row.col.f32.f16.f16.f32 "
                    "{%0,%1,%2,%3}, {%4,%5,%6,%7}, {%8,%9}, {%0,%1,%2,%3};"
                    : "+f"(o[hn][0]), "+f"(o[hn][1]), "+f"(o[hn][2]), "+f"(o[hn][3])
                    : "r"(pl[2 * kk]), "r"(pr[2 * kk]),
                      "r"(pl[2 * kk + 1]), "r"(pr[2 * kk + 1]),
                      "r"(b0), "r"(b1));
            }
        }
    }

    // ---- l reduction across the quad (lanes sharing a row) ----
    l0 += __shfl_xor_sync(0xffffffffu, l0, 1);
    l0 += __shfl_xor_sync(0xffffffffu, l0, 2);
    l1 += __shfl_xor_sync(0xffffffffu, l1, 1);
    l1 += __shfl_xor_sync(0xffffffffu, l1, 2);
    const float inv0 = 1.0f / l0;
    const float inv1 = 1.0f / l1;

    float* o0 = out + ((size_t)b * TT + r0) * HH + cql;
    float* o1 = out + ((size_t)b * TT + r1) * HH + cql;
    #pragma unroll
    for (int hn = 0; hn < 8; ++hn) {
        *(float2*)(o0 + hn * 8) = make_float2(o[hn][0] * inv0, o[hn][1] * inv0);
        *(float2*)(o1 + hn * 8) = make_float2(o[hn][2] * inv1, o[hn][3] * inv1);
    }
}

// ---------------------------------------------------------------------------
extern "C" void kernel_launch(void* const* d_in, const int* in_sizes, int n_in,
                              void* d_out, int out_size)
{
    (void)in_sizes; (void)n_in; (void)out_size;
    const float* x  = (const float*)d_in[0];
    const float* Wq = (const float*)d_in[1];
    const float* Wk = (const float*)d_in[2];
    const float* Wv = (const float*)d_in[3];
    float* out = (float*)d_out;

    proj_kernel<<<(BB * TT) / 64, 256>>>(x, Wq, Wk, Wv);
    flash_mma<<<dim3(TT / 128, BB), 256>>>(out);
}

// round 4
// speedup vs baseline: 4.0405x; 1.1674x over previous
#include <cuda_runtime.h>
#include <cuda_fp16.h>
#include <cstdint>

#define BB 8
#define TT 4096
#define DD 512
#define HH 64

// fp16 projected tensors (device globals: allocation-free)
__device__ __half g_qh[BB * TT * HH];           // [b*T + t][h]
__device__ __half g_kh[BB * TT * HH];           // [b*T + t][h]
__device__ __half g_vt[BB * HH * TT];           // [b][h][t]  (V transposed)

__device__ __forceinline__ uint32_t smem_to_u32(const void* p) {
    uint32_t a;
    asm("{ .reg .u64 t; cvta.to.shared.u64 t, %1; cvt.u32.u64 %0, t; }" : "=r"(a) : "l"(p));
    return a;
}
__device__ __forceinline__ float fex2(float x) {
    float y; asm("ex2.approx.ftz.f32 %0, %1;" : "=f"(y) : "f"(x)); return y;
}
#define CP_ASYNC16(dst, src) \
    asm volatile("cp.async.cg.shared.global [%0], [%1], 16;" :: "r"(dst), "l"(src))
#define CP_COMMIT() asm volatile("cp.async.commit_group;")
#define CP_WAIT0()  asm volatile("cp.async.wait_group 0;" ::: "memory")

#define MMA_F16(d, a, b0, b1) \
    asm volatile("mma.sync.aligned.m16n8k16.row.col.f32.f16.f16.f32 " \
        "{%0,%1,%2,%3}, {%4,%5,%6,%7}, {%8,%9}, {%0,%1,%2,%3};" \
        : "+f"((d)[0]), "+f"((d)[1]), "+f"((d)[2]), "+f"((d)[3]) \
        : "r"((a)[0]), "r"((a)[1]), "r"((a)[2]), "r"((a)[3]), "r"(b0), "r"(b1))

// ---------------------------------------------------------------------------
// Kernel 1: QKV projection on tensor cores (fp16 in, fp32 accum).
// CTA: 256 thr / 8 warps (2m x 4n). Tile 128 rows x 192 cols, K chunks of 64.
// ---------------------------------------------------------------------------
#define XP 72    // halves pitch of X tile (144B: conflict-free ldmatrix)
#define WP 200   // halves pitch of W tile (400B: 4-bank shift/row)
#define VP 136   // halves pitch of V staging

__global__ __launch_bounds__(256) void proj_mma(
    const float* __restrict__ x,
    const float* __restrict__ Wq,
    const float* __restrict__ Wk,
    const float* __restrict__ Wv)
{
    __shared__ __align__(16) char pool[128 * XP * 2 + 64 * WP * 2];
    __half* Xh  = (__half*)pool;                       // [128][XP]
    __half* Wh  = (__half*)(pool + 128 * XP * 2);      // [64][WP]
    __half* Vst = (__half*)pool;                       // [64][VP] (reuses Xh)

    const int tid  = threadIdx.x;
    const int warp = tid >> 5;
    const int lane = tid & 31;
    const int wm   = warp >> 2;        // 0..1  (64 rows each)
    const int wn   = warp & 3;         // 0..3  (48 cols each)
    const int row0 = blockIdx.x * 128;

    const uint32_t xb = smem_to_u32(Xh);
    const uint32_t wb = smem_to_u32(Wh);

    float acc[4][6][4];
    #pragma unroll
    for (int mt = 0; mt < 4; ++mt)
        #pragma unroll
        for (int nt = 0; nt < 6; ++nt)
            acc[mt][nt][0] = acc[mt][nt][1] = acc[mt][nt][2] = acc[mt][nt][3] = 0.f;

    for (int kc = 0; kc < 8; ++kc) {
        const int k0g = kc * 64;
        // ---- X chunk: 128 rows x 64 fp32 -> fp16 SMEM ----
        #pragma unroll
        for (int it = 0; it < 8; ++it) {
            int idx = tid + it * 256;      // 0..2047
            int r = idx >> 4, c = idx & 15;
            float4 v = *(const float4*)&x[(size_t)(row0 + r) * DD + k0g + c * 4];
            *(__half2*)&Xh[r * XP + c * 4]     = __floats2half2_rn(v.x, v.y);
            *(__half2*)&Xh[r * XP + c * 4 + 2] = __floats2half2_rn(v.z, v.w);
        }
        // ---- W chunk: 3 x (64 k x 64 n) fp32 -> fp16 SMEM [k][n] ----
        #pragma unroll
        for (int m = 0; m < 3; ++m) {
            const float* W = (m == 0) ? Wq : ((m == 1) ? Wk : Wv);
            #pragma unroll
            for (int it = 0; it < 4; ++it) {
                int idx = tid + it * 256;  // 0..1023
                int r = idx >> 4, c = idx & 15;
                float4 v = *(const float4*)&W[(size_t)(k0g + r) * HH + c * 4];
                *(__half2*)&Wh[r * WP + m * 64 + c * 4]     = __floats2half2_rn(v.x, v.y);
                *(__half2*)&Wh[r * WP + m * 64 + c * 4 + 2] = __floats2half2_rn(v.z, v.w);
            }
        }
        __syncthreads();

        #pragma unroll
        for (int ks = 0; ks < 4; ++ks) {
            uint32_t a[4][4];
            #pragma unroll
            for (int mt = 0; mt < 4; ++mt) {
                int row = wm * 64 + mt * 16 + (lane & 7) + ((lane >> 3) & 1) * 8;
                int col = ks * 16 + ((lane >> 4) << 3);
                uint32_t ad = xb + (uint32_t)(row * XP + col) * 2;
                asm volatile("ldmatrix.sync.aligned.m8n8.x4.shared.b16 {%0,%1,%2,%3}, [%4];"
                    : "=r"(a[mt][0]), "=r"(a[mt][1]), "=r"(a[mt][2]), "=r"(a[mt][3])
                    : "r"(ad));
            }
            #pragma unroll
            for (int nt = 0; nt < 6; ++nt) {
                uint32_t b0, b1;
                uint32_t ad = wb +
                    (uint32_t)((ks * 16 + (lane & 15)) * WP + wn * 48 + nt * 8) * 2;
                asm volatile("ldmatrix.sync.aligned.m8n8.x2.trans.shared.b16 {%0,%1}, [%2];"
                    : "=r"(b0), "=r"(b1) : "r"(ad));
                #pragma unroll
                for (int mt = 0; mt < 4; ++mt)
                    MMA_F16(acc[mt][nt], a[mt], b0, b1);
            }
        }
        __syncthreads();
    }

    // ---- store Q/K direct; stage V into SMEM for transposed coalesced write ----
    const int rA = lane >> 2;
    const int cA = (lane & 3) * 2;
    #pragma unroll
    for (int mt = 0; mt < 4; ++mt) {
        #pragma unroll
        for (int nt = 0; nt < 6; ++nt) {
            const int n0 = wn * 48 + nt * 8 + cA;
            const int r  = wm * 64 + mt * 16 + rA;
            if (n0 < 128) {
                __half* dst = (n0 < 64) ? g_qh : g_kh;
                const int nn = n0 & 63;
                *(__half2*)&dst[(size_t)(row0 + r) * HH + nn] =
                    __floats2half2_rn(acc[mt][nt][0], acc[mt][nt][1]);
                *(__half2*)&dst[(size_t)(row0 + r + 8) * HH + nn] =
                    __floats2half2_rn(acc[mt][nt][2], acc[mt][nt][3]);
            } else {
                const int h = n0 - 128;
                Vst[h * VP + r]           = __float2half(acc[mt][nt][0]);
                Vst[(h + 1) * VP + r]     = __float2half(acc[mt][nt][1]);
                Vst[h * VP + r + 8]       = __float2half(acc[mt][nt][2]);
                Vst[(h + 1) * VP + r + 8] = __float2half(acc[mt][nt][3]);
            }
        }
    }
    __syncthreads();

    const int b  = row0 >> 12;
    const int t0 = row0 & (TT - 1);
    #pragma unroll
    for (int it = 0; it < 4; ++it) {
        int idx = tid + it * 256;          // 0..1023
        int h = idx >> 4, tc = (idx & 15) * 8;
        uint4 v = *(uint4*)&Vst[h * VP + tc];
        *(uint4*)&g_vt[((size_t)b * HH + h) * TT + t0 + tc] = v;
    }
}

// ---------------------------------------------------------------------------
// Kernel 2: flash attention, mma.sync + cp.async double-buffered K/V.
// One __syncthreads per key tile; load latency hidden behind compute.
// ---------------------------------------------------------------------------
#define PITCH 72
#define QOFF  0
#define KOFF0 18432
#define KOFF1 27648
#define VOFF0 36864
#define VOFF1 46080
#define FLASH_SMEM 55296

__device__ __forceinline__ void kv_cp(uint32_t smb, const __half* kg, const __half* vtg,
                                      int j0, int buf, int tid)
{
    const uint32_t kb = smb + (buf ? KOFF1 : KOFF0);
    const uint32_t vb = smb + (buf ? VOFF1 : VOFF0);
    #pragma unroll
    for (int it = 0; it < 2; ++it) {
        int idx = tid + it * 256;          // 0..511
        int r = idx >> 3, c = idx & 7;
        CP_ASYNC16(kb + (uint32_t)(r * (PITCH * 2) + c * 16),
                   kg + (size_t)(j0 + r) * HH + c * 8);
        CP_ASYNC16(vb + (uint32_t)(r * (PITCH * 2) + c * 16),
                   vtg + (size_t)r * TT + j0 + c * 8);
    }
}

__global__ __launch_bounds__(256, 2) void flash_mma(float* __restrict__ out)
{
    extern __shared__ __align__(16) char sm[];
    const uint32_t smb = smem_to_u32(sm);

    const int tid  = threadIdx.x;
    const int warp = tid >> 5;
    const int lane = tid & 31;
    const int b    = blockIdx.y;
    const int qi0  = (int)(gridDim.x - 1 - blockIdx.x) * 128;   // biggest first

    const __half* qg  = g_qh + ((size_t)b * TT + qi0) * HH;
    const __half* kg  = g_kh + (size_t)b * TT * HH;
    const __half* vtg = g_vt + (size_t)b * HH * TT;

    // ---- prologue: Q + tile 0 via cp.async ----
    #pragma unroll
    for (int it = 0; it < 4; ++it) {
        int idx = tid + it * 256;          // 0..1023
        int r = idx >> 3, c = idx & 7;
        CP_ASYNC16(smb + QOFF + (uint32_t)(r * (PITCH * 2) + c * 16),
                   qg + (size_t)r * HH + c * 8);
    }
    kv_cp(smb, kg, vtg, 0, 0, tid);
    CP_COMMIT();
    CP_WAIT0();
    __syncthreads();

    // ---- Q A-fragments (resident all kernel) ----
    const int mrow = warp * 16;
    uint32_t aq[4][4];
    {
        int row = mrow + (lane & 7) + ((lane >> 3) & 1) * 8;
        int col = ((lane >> 4) << 3);
        #pragma unroll
        for (int ks = 0; ks < 4; ++ks) {
            uint32_t ad = smb + QOFF + (uint32_t)(row * PITCH + ks * 16 + col) * 2;
            asm volatile("ldmatrix.sync.aligned.m8n8.x4.shared.b16 {%0,%1,%2,%3}, [%4];"
                : "=r"(aq[ks][0]), "=r"(aq[ks][1]), "=r"(aq[ks][2]), "=r"(aq[ks][3])
                : "r"(ad));
        }
    }

    const int r0  = qi0 + mrow + (lane >> 2);
    const int r1  = r0 + 8;
    const int cql = (lane & 3) * 2;

    float o[8][4];
    #pragma unroll
    for (int n = 0; n < 8; ++n)
        #pragma unroll
        for (int i = 0; i < 4; ++i) o[n][i] = 0.f;
    float l0 = 0.f, l1 = 0.f;

    const int brow = lane & 7;
    const int bcol = lane & 8;
    const float SC = 0.044194173824159216f * 1.4426950408889634f;  // scale*log2(e)

    const int ntiles = qi0 / 64 + 2;

    for (int t = 0; t < ntiles; ++t) {
        if (t + 1 < ntiles)
            kv_cp(smb, kg, vtg, (t + 1) * 64, (t + 1) & 1, tid);
        CP_COMMIT();

        const uint32_t kbase = smb + ((t & 1) ? KOFF1 : KOFF0);
        const uint32_t vbase = smb + ((t & 1) ? VOFF1 : VOFF0);
        const int j0 = t * 64;

        // ---- S = Q K^T ----
        float s[8][4];
        #pragma unroll
        for (int n = 0; n < 8; ++n) {
            s[n][0] = s[n][1] = s[n][2] = s[n][3] = 0.f;
            #pragma unroll
            for (int ks = 0; ks < 4; ++ks) {
                uint32_t b0, b1;
                uint32_t ad = kbase + (uint32_t)((n * 8 + brow) * PITCH + ks * 16 + bcol) * 2;
                asm volatile("ldmatrix.sync.aligned.m8n8.x2.shared.b16 {%0,%1}, [%2];"
                    : "=r"(b0), "=r"(b1) : "r"(ad));
                MMA_F16(s[n], aq[ks], b0, b1);
            }
        }

        // ---- exp + causal mask + pack P ----
        uint32_t pl[8], pr[8];
        #pragma unroll
        for (int n = 0; n < 8; ++n) {
            const int cb = j0 + n * 8 + cql;
            float e0 = fex2(s[n][0] * SC); if (cb     > r0) e0 = 0.f;
            float e1 = fex2(s[n][1] * SC); if (cb + 1 > r0) e1 = 0.f;
            float e2 = fex2(s[n][2] * SC); if (cb     > r1) e2 = 0.f;
            float e3 = fex2(s[n][3] * SC); if (cb + 1 > r1) e3 = 0.f;
            l0 += e0 + e1;
            l1 += e2 + e3;
            asm("cvt.rn.f16x2.f32 %0, %1, %2;" : "=r"(pl[n]) : "f"(e1), "f"(e0));
            asm("cvt.rn.f16x2.f32 %0, %1, %2;" : "=r"(pr[n]) : "f"(e3), "f"(e2));
        }

        // ---- O += P V ----
        #pragma unroll
        for (int hn = 0; hn < 8; ++hn) {
            #pragma unroll
            for (int kk = 0; kk < 4; ++kk) {
                uint32_t b0, b1;
                uint32_t ad = vbase + (uint32_t)((hn * 8 + brow) * PITCH + kk * 16 + bcol) * 2;
                asm volatile("ldmatrix.sync.aligned.m8n8.x2.shared.b16 {%0,%1}, [%2];"
                    : "=r"(b0), "=r"(b1) : "r"(ad));
                asm volatile("mma.sync.aligned.m16n8k16.row.col.f32.f16.f16.f32 "
                    "{%0,%1,%2,%3}, {%4,%5,%6,%7}, {%8,%9}, {%0,%1,%2,%3};"
                    : "+f"(o[hn][0]), "+f"(o[hn][1]), "+f"(o[hn][2]), "+f"(o[hn][3])
                    : "r"(pl[2 * kk]), "r"(pr[2 * kk]),
                      "r"(pl[2 * kk + 1]), "r"(pr[2 * kk + 1]),
                      "r"(b0), "r"(b1));
            }
        }

        CP_WAIT0();
        __syncthreads();
    }

    // ---- l reduction across quad, normalize, store ----
    l0 += __shfl_xor_sync(0xffffffffu, l0, 1);
    l0 += __shfl_xor_sync(0xffffffffu, l0, 2);
    l1 += __shfl_xor_sync(0xffffffffu, l1, 1);
    l1 += __shfl_xor_sync(0xffffffffu, l1, 2);
    const float inv0 = 1.0f / l0;
    const float inv1 = 1.0f / l1;

    float* o0 = out + ((size_t)b * TT + r0) * HH + cql;
    float* o1 = out + ((size_t)b * TT + r1) * HH + cql;
    #pragma unroll
    for (int hn = 0; hn < 8; ++hn) {
        *(float2*)(o0 + hn * 8) = make_float2(o[hn][0] * inv0, o[hn][1] * inv0);
        *(float2*)(o1 + hn * 8) = make_float2(o[hn][2] * inv1, o[hn][3] * inv1);
    }
}

// ---------------------------------------------------------------------------
extern "C" void kernel_launch(void* const* d_in, const int* in_sizes, int n_in,
                              void* d_out, int out_size)
{
    (void)in_sizes; (void)n_in; (void)out_size;
    const float* x  = (const float*)d_in[0];
    const float* Wq = (const float*)d_in[1];
    const float* Wk = (const float*)d_in[2];
    const float* Wv = (const float*)d_in[3];
    float* out = (float*)d_out;

    cudaFuncSetAttribute(flash_mma, cudaFuncAttributeMaxDynamicSharedMemorySize, FLASH_SMEM);

    proj_mma<<<(BB * TT) / 128, 256>>>(x, Wq, Wk, Wv);
    flash_mma<<<dim3(TT / 128, BB), 256, FLASH_SMEM>>>(out);
}

// round 7
// speedup vs baseline: 7.6655x; 1.8972x over previous
#include <cuda_runtime.h>
#include <cuda_fp16.h>
#include <cstdint>

#define BB 8
#define TT 4096
#define DD 512
#define HH 64

// device-global scratch (allocation-free)
__device__ __half g_qh[BB * TT * HH];            // [b*T + t][h]
__device__ __half g_kh[BB * TT * HH];            // [b*T + t][h]
__device__ __half g_vt[BB * HH * TT];            // [b][h][t]  (V transposed)
__device__ __half g_xh[BB * TT * DD];            // fp16 copy of inputs
__device__ __half g_w3h[DD * 192];               // fp16 W interleaved [k][m*64+n]
#define NCHUNK 144                               // key-chunks per batch
__device__ float g_po[BB * NCHUNK * 128 * 64];   // partial O (unnormalized)
__device__ float g_pl[BB * NCHUNK * 128];        // partial l

__device__ __forceinline__ uint32_t smem_to_u32(const void* p) {
    uint32_t a;
    asm("{ .reg .u64 t; cvta.to.shared.u64 t, %1; cvt.u32.u64 %0, t; }" : "=r"(a) : "l"(p));
    return a;
}
__device__ __forceinline__ float fex2(float x) {
    float y; asm("ex2.approx.ftz.f32 %0, %1;" : "=f"(y) : "f"(x)); return y;
}
#define CP_ASYNC16(dst, src) \
    asm volatile("cp.async.cg.shared.global [%0], [%1], 16;" :: "r"(dst), "l"(src))
#define CP_COMMIT() asm volatile("cp.async.commit_group;")
#define CP_WAIT0()  asm volatile("cp.async.wait_group 0;" ::: "memory")

#define MMA_F16(d, a, b0, b1) \
    asm volatile("mma.sync.aligned.m16n8k16.row.col.f32.f16.f16.f32 " \
        "{%0,%1,%2,%3}, {%4,%5,%6,%7}, {%8,%9}, {%0,%1,%2,%3};" \
        : "+f"((d)[0]), "+f"((d)[1]), "+f"((d)[2]), "+f"((d)[3]) \
        : "r"((a)[0]), "r"((a)[1]), "r"((a)[2]), "r"((a)[3]), "r"(b0), "r"(b1))

// ---------------------------------------------------------------------------
// fp16 pre-conversion
// ---------------------------------------------------------------------------
__global__ __launch_bounds__(256) void conv_x(const float* __restrict__ x)
{
    size_t i = ((size_t)blockIdx.x * 256 + threadIdx.x) * 8;
    float4 a = *(const float4*)(x + i);
    float4 b = *(const float4*)(x + i + 4);
    __half2 h0 = __floats2half2_rn(a.x, a.y);
    __half2 h1 = __floats2half2_rn(a.z, a.w);
    __half2 h2 = __floats2half2_rn(b.x, b.y);
    __half2 h3 = __floats2half2_rn(b.z, b.w);
    uint4 o;
    o.x = *(uint32_t*)&h0; o.y = *(uint32_t*)&h1;
    o.z = *(uint32_t*)&h2; o.w = *(uint32_t*)&h3;
    *(uint4*)&g_xh[i] = o;
}

__global__ __launch_bounds__(256) void conv_w(
    const float* __restrict__ Wq, const float* __restrict__ Wk, const float* __restrict__ Wv)
{
    int gid = blockIdx.x * 256 + threadIdx.x;      // 12288 threads, 8 halves each
    int col = (gid * 8) % 192;
    int k   = (gid * 8) / 192;
    int m   = col / 64;
    int n   = col % 64;
    const float* W = (m == 0) ? Wq : ((m == 1) ? Wk : Wv);
    float4 a = *(const float4*)&W[(size_t)k * HH + n];
    float4 b = *(const float4*)&W[(size_t)k * HH + n + 4];
    __half2 h0 = __floats2half2_rn(a.x, a.y);
    __half2 h1 = __floats2half2_rn(a.z, a.w);
    __half2 h2 = __floats2half2_rn(b.x, b.y);
    __half2 h3 = __floats2half2_rn(b.z, b.w);
    uint4 o;
    o.x = *(uint32_t*)&h0; o.y = *(uint32_t*)&h1;
    o.z = *(uint32_t*)&h2; o.w = *(uint32_t*)&h3;
    *(uint4*)&g_w3h[(size_t)k * 192 + col] = o;
}

// ---------------------------------------------------------------------------
// Kernel 1: QKV projection, tensor cores, cp.async double-buffered fp16 tiles
// ---------------------------------------------------------------------------
#define XP 72    // X tile pitch (halves)
#define WP 200   // W tile pitch (halves)
#define VP 136   // V staging pitch (halves)
#define PX0 0
#define PX1 18432
#define PW0 36864
#define PW1 62464
#define PROJ_SMEM 88064

__device__ __forceinline__ void proj_cp(uint32_t smb, int kc, int buf, int row0, int tid)
{
    const __half* xsrc = g_xh + (size_t)row0 * DD + kc * 64;
    const uint32_t xb = smb + (buf ? PX1 : PX0);
    #pragma unroll
    for (int it = 0; it < 4; ++it) {
        int idx = tid + it * 256;                  // 0..1023
        int r = idx >> 3, c = idx & 7;
        CP_ASYNC16(xb + (uint32_t)(r * (XP * 2) + c * 16), xsrc + (size_t)r * DD + c * 8);
    }
    const __half* wsrc = g_w3h + (size_t)(kc * 64) * 192;
    const uint32_t wb = smb + (buf ? PW1 : PW0);
    #pragma unroll
    for (int it = 0; it < 6; ++it) {
        int idx = tid + it * 256;                  // 0..1535
        int r = idx / 24, c = idx % 24;
        CP_ASYNC16(wb + (uint32_t)(r * (WP * 2) + c * 16), wsrc + (size_t)r * 192 + c * 8);
    }
}

__global__ __launch_bounds__(256) void proj_mma(int dummy)
{
    extern __shared__ __align__(16) char psm[];
    const uint32_t smb = smem_to_u32(psm);
    __half* Vst = (__half*)psm;                    // reuses X buf 0 region

    const int tid  = threadIdx.x;
    const int warp = tid >> 5;
    const int lane = tid & 31;
    const int wm   = warp >> 2;
    const int wn   = warp & 3;
    const int row0 = blockIdx.x * 128;

    float acc[4][6][4];
    #pragma unroll
    for (int mt = 0; mt < 4; ++mt)
        #pragma unroll
        for (int nt = 0; nt < 6; ++nt)
            acc[mt][nt][0] = acc[mt][nt][1] = acc[mt][nt][2] = acc[mt][nt][3] = 0.f;

    proj_cp(smb, 0, 0, row0, tid);
    CP_COMMIT();
    CP_WAIT0();
    __syncthreads();

    for (int kc = 0; kc < 8; ++kc) {
        if (kc < 7) { proj_cp(smb, kc + 1, (kc + 1) & 1, row0, tid); CP_COMMIT(); }

        const uint32_t xb = smb + ((kc & 1) ? PX1 : PX0);
        const uint32_t wb = smb + ((kc & 1) ? PW1 : PW0);

        #pragma unroll
        for (int ks = 0; ks < 4; ++ks) {
            uint32_t a[4][4];
            #pragma unroll
            for (int mt = 0; mt < 4; ++mt) {
                int row = wm * 64 + mt * 16 + (lane & 7) + ((lane >> 3) & 1) * 8;
                int col = ks * 16 + ((lane >> 4) << 3);
                uint32_t ad = xb + (uint32_t)(row * XP + col) * 2;
                asm volatile("ldmatrix.sync.aligned.m8n8.x4.shared.b16 {%0,%1,%2,%3}, [%4];"
                    : "=r"(a[mt][0]), "=r"(a[mt][1]), "=r"(a[mt][2]), "=r"(a[mt][3])
                    : "r"(ad));
            }
            #pragma unroll
            for (int nt = 0; nt < 6; ++nt) {
                uint32_t b0, b1;
                uint32_t ad = wb +
                    (uint32_t)((ks * 16 + (lane & 15)) * WP + wn * 48 + nt * 8) * 2;
                asm volatile("ldmatrix.sync.aligned.m8n8.x2.trans.shared.b16 {%0,%1}, [%2];"
                    : "=r"(b0), "=r"(b1) : "r"(ad));
                #pragma unroll
                for (int mt = 0; mt < 4; ++mt)
                    MMA_F16(acc[mt][nt], a[mt], b0, b1);
            }
        }
        if (kc < 7) CP_WAIT0();
        __syncthreads();
    }

    // ---- store Q/K direct; stage V for transposed coalesced write ----
    const int rA = lane >> 2;
    const int cA = (lane & 3) * 2;
    #pragma unroll
    for (int mt = 0; mt < 4; ++mt) {
        #pragma unroll
        for (int nt = 0; nt < 6; ++nt) {
            const int n0 = wn * 48 + nt * 8 + cA;
            const int r  = wm * 64 + mt * 16 + rA;
            if (n0 < 128) {
                __half* dst = (n0 < 64) ? g_qh : g_kh;
                const int nn = n0 & 63;
                *(__half2*)&dst[(size_t)(row0 + r) * HH + nn] =
                    __floats2half2_rn(acc[mt][nt][0], acc[mt][nt][1]);
                *(__half2*)&dst[(size_t)(row0 + r + 8) * HH + nn] =
                    __floats2half2_rn(acc[mt][nt][2], acc[mt][nt][3]);
            } else {
                const int h = n0 - 128;
                Vst[h * VP + r]           = __float2half(acc[mt][nt][0]);
                Vst[(h + 1) * VP + r]     = __float2half(acc[mt][nt][1]);
                Vst[h * VP + r + 8]       = __float2half(acc[mt][nt][2]);
                Vst[(h + 1) * VP + r + 8] = __float2half(acc[mt][nt][3]);
            }
        }
    }
    __syncthreads();

    const int b  = row0 >> 12;
    const int t0 = row0 & (TT - 1);
    #pragma unroll
    for (int it = 0; it < 4; ++it) {
        int idx = tid + it * 256;
        int h = idx >> 4, tc = (idx & 15) * 8;
        uint4 v = *(uint4*)&Vst[h * VP + tc];
        *(uint4*)&g_vt[((size_t)b * HH + h) * TT + t0 + tc] = v;
    }
}

// ---------------------------------------------------------------------------
// Kernel 2: split-K flash chunks. Item = (b, qblock g, key-chunk c of <=8 tiles)
// ---------------------------------------------------------------------------
#define PITCH 72
#define QOFF  0
#define KOFF0 18432
#define KOFF1 27648
#define VOFF0 36864
#define VOFF1 46080
#define FLASH_SMEM 55296

__device__ __forceinline__ void kv_cp(uint32_t smb, const __half* kg, const __half* vtg,
                                      int j0, int buf, int tid)
{
    const uint32_t kb = smb + (buf ? KOFF1 : KOFF0);
    const uint32_t vb = smb + (buf ? VOFF1 : VOFF0);
    #pragma unroll
    for (int it = 0; it < 2; ++it) {
        int idx = tid + it * 256;
        int r = idx >> 3, c = idx & 7;
        CP_ASYNC16(kb + (uint32_t)(r * (PITCH * 2) + c * 16),
                   kg + (size_t)(j0 + r) * HH + c * 8);
        CP_ASYNC16(vb + (uint32_t)(r * (PITCH * 2) + c * 16),
                   vtg + (size_t)r * TT + j0 + c * 8);
    }
}

__global__ __launch_bounds__(256, 2) void flash_chunk(int dummy)
{
    extern __shared__ __align__(16) char sm[];
    const uint32_t smb = smem_to_u32(sm);

    const int tid  = threadIdx.x;
    const int warp = tid >> 5;
    const int lane = tid & 31;
    const int b    = blockIdx.y;

    // decode work item -> (g, c)
    int g = 0, cch = 0;
    {
        int it = blockIdx.x, off = 0;
        #pragma unroll 1
        for (int gg = 0; gg < 32; ++gg) {
            int cg = (2 * gg + 9) >> 3;
            if (it < off + cg) { g = gg; cch = it - off; break; }
            off += cg;
        }
    }
    const int qi0 = g * 128;
    const int t0  = cch * 8;
    const int t1  = min(t0 + 8, 2 * g + 2);

    const __half* qg  = g_qh + ((size_t)b * TT + qi0) * HH;
    const __half* kg  = g_kh + (size_t)b * TT * HH;
    const __half* vtg = g_vt + (size_t)b * HH * TT;

    // prologue: Q + first K/V tile
    #pragma unroll
    for (int it = 0; it < 4; ++it) {
        int idx = tid + it * 256;
        int r = idx >> 3, c = idx & 7;
        CP_ASYNC16(smb + QOFF + (uint32_t)(r * (PITCH * 2) + c * 16),
                   qg + (size_t)r * HH + c * 8);
    }
    kv_cp(smb, kg, vtg, t0 * 64, t0 & 1, tid);
    CP_COMMIT();
    CP_WAIT0();
    __syncthreads();

    // Q A-fragments
    const int mrow = warp * 16;
    uint32_t aq[4][4];
    {
        int row = mrow + (lane & 7) + ((lane >> 3) & 1) * 8;
        int col = ((lane >> 4) << 3);
        #pragma unroll
        for (int ks = 0; ks < 4; ++ks) {
            uint32_t ad = smb + QOFF + (uint32_t)(row * PITCH + ks * 16 + col) * 2;
            asm volatile("ldmatrix.sync.aligned.m8n8.x4.shared.b16 {%0,%1,%2,%3}, [%4];"
                : "=r"(aq[ks][0]), "=r"(aq[ks][1]), "=r"(aq[ks][2]), "=r"(aq[ks][3])
                : "r"(ad));
        }
    }

    const int lr0 = mrow + (lane >> 2);           // local rows
    const int lr1 = lr0 + 8;
    const int r0g = qi0 + lr0;                    // global rows (for mask)
    const int r1g = r0g + 8;
    const int cql = (lane & 3) * 2;

    float o[8][4];
    #pragma unroll
    for (int n = 0; n < 8; ++n)
        #pragma unroll
        for (int i = 0; i < 4; ++i) o[n][i] = 0.f;
    float l0 = 0.f, l1 = 0.f;

    // x4 B-frag address components (two 8-row tiles per ldmatrix)
    const int b4r = ((lane >> 4) << 3) + (lane & 7);
    const int b4c = ((lane >> 3) & 1) * 8;
    const float SC = 0.044194173824159216f * 1.4426950408889634f;

    for (int t = t0; t < t1; ++t) {
        if (t + 1 < t1) { kv_cp(smb, kg, vtg, (t + 1) * 64, (t + 1) & 1, tid); CP_COMMIT(); }

        const uint32_t kbase = smb + ((t & 1) ? KOFF1 : KOFF0);
        const uint32_t vbase = smb + ((t & 1) ? VOFF1 : VOFF0);
        const int j0 = t * 64;

        // ---- S = Q K^T (x4 B loads: 2 j-tiles per ldmatrix) ----
        float s[8][4];
        #pragma unroll
        for (int n = 0; n < 8; n += 2) {
            s[n][0] = s[n][1] = s[n][2] = s[n][3] = 0.f;
            s[n+1][0] = s[n+1][1] = s[n+1][2] = s[n+1][3] = 0.f;
            #pragma unroll
            for (int ks = 0; ks < 4; ++ks) {
                uint32_t b0, b1, b2, b3;
                uint32_t ad = kbase + (uint32_t)((n * 8 + b4r) * PITCH + ks * 16 + b4c) * 2;
                asm volatile("ldmatrix.sync.aligned.m8n8.x4.shared.b16 {%0,%1,%2,%3}, [%4];"
                    : "=r"(b0), "=r"(b1), "=r"(b2), "=r"(b3) : "r"(ad));
                MMA_F16(s[n],     aq[ks], b0, b1);
                MMA_F16(s[n + 1], aq[ks], b2, b3);
            }
        }

        // ---- exp (+ mask only on diagonal tiles) + pack P ----
        uint32_t pl[8], pr[8];
        if (t >= 2 * g) {
            #pragma unroll
            for (int n = 0; n < 8; ++n) {
                const int cb = j0 + n * 8 + cql;
                float e0 = fex2(s[n][0] * SC); if (cb     > r0g) e0 = 0.f;
                float e1 = fex2(s[n][1] * SC); if (cb + 1 > r0g) e1 = 0.f;
                float e2 = fex2(s[n][2] * SC); if (cb     > r1g) e2 = 0.f;
                float e3 = fex2(s[n][3] * SC); if (cb + 1 > r1g) e3 = 0.f;
                l0 += e0 + e1;
                l1 += e2 + e3;
                asm("cvt.rn.f16x2.f32 %0, %1, %2;" : "=r"(pl[n]) : "f"(e1), "f"(e0));
                asm("cvt.rn.f16x2.f32 %0, %1, %2;" : "=r"(pr[n]) : "f"(e3), "f"(e2));
            }
        } else {
            #pragma unroll
            for (int n = 0; n < 8; ++n) {
                float e0 = fex2(s[n][0] * SC);
                float e1 = fex2(s[n][1] * SC);
                float e2 = fex2(s[n][2] * SC);
                float e3 = fex2(s[n][3] * SC);
                l0 += e0 + e1;
                l1 += e2 + e3;
                asm("cvt.rn.f16x2.f32 %0, %1, %2;" : "=r"(pl[n]) : "f"(e1), "f"(e0));
                asm("cvt.rn.f16x2.f32 %0, %1, %2;" : "=r"(pr[n]) : "f"(e3), "f"(e2));
            }
        }

        // ---- O += P V (x4 B loads: 2 h-tiles per ldmatrix) ----
        #pragma unroll
        for (int hn = 0; hn < 8; hn += 2) {
            #pragma unroll
            for (int kk = 0; kk < 4; ++kk) {
                uint32_t b0, b1, b2, b3;
                uint32_t ad = vbase + (uint32_t)((hn * 8 + b4r) * PITCH + kk * 16 + b4c) * 2;
                asm volatile("ldmatrix.sync.aligned.m8n8.x4.shared.b16 {%0,%1,%2,%3}, [%4];"
                    : "=r"(b0), "=r"(b1), "=r"(b2), "=r"(b3) : "r"(ad));
                uint32_t ap[4] = {pl[2*kk], pr[2*kk], pl[2*kk+1], pr[2*kk+1]};
                MMA_F16(o[hn],     ap, b0, b1);
                MMA_F16(o[hn + 1], ap, b2, b3);
            }
        }

        if (t + 1 < t1) CP_WAIT0();
        __syncthreads();
    }

    // ---- epilogue: quad-reduce l, store unnormalized partials ----
    l0 += __shfl_xor_sync(0xffffffffu, l0, 1);
    l0 += __shfl_xor_sync(0xffffffffu, l0, 2);
    l1 += __shfl_xor_sync(0xffffffffu, l1, 1);
    l1 += __shfl_xor_sync(0xffffffffu, l1, 2);

    const int item = b * NCHUNK + (int)blockIdx.x;
    if ((lane & 3) == 0) {
        g_pl[(size_t)item * 128 + lr0] = l0;
        g_pl[(size_t)item * 128 + lr1] = l1;
    }
    float* po = g_po + (size_t)item * (128 * 64);
    float* p0 = po + lr0 * 64 + cql;
    float* p1 = po + lr1 * 64 + cql;
    #pragma unroll
    for (int hn = 0; hn < 8; ++hn) {
        *(float2*)(p0 + hn * 8) = make_float2(o[hn][0], o[hn][1]);
        *(float2*)(p1 + hn * 8) = make_float2(o[hn][2], o[hn][3]);
    }
}

// ---------------------------------------------------------------------------
// Kernel 3: combine partials and normalize
// ---------------------------------------------------------------------------
__global__ __launch_bounds__(256) void combine_kernel(float* __restrict__ out)
{
    const int g = blockIdx.x, b = blockIdx.y;
    int off = 0;
    #pragma unroll 1
    for (int gg = 0; gg < 32; ++gg) { if (gg < g) off += (2 * gg + 9) >> 3; }
    const int nc   = (2 * g + 9) >> 3;
    const int base = b * NCHUNK + off;

    const int tid = threadIdx.x;
    const int r   = tid >> 1;
    const int c0  = (tid & 1) * 32;

    float l = 0.f;
    #pragma unroll 1
    for (int c = 0; c < nc; ++c) l += g_pl[(size_t)(base + c) * 128 + r];
    const float inv = 1.0f / l;

    float4 acc[8];
    #pragma unroll
    for (int j = 0; j < 8; ++j) acc[j] = make_float4(0.f, 0.f, 0.f, 0.f);
    #pragma unroll 1
    for (int c = 0; c < nc; ++c) {
        const float* p = g_po + (size_t)(base + c) * (128 * 64) + r * 64 + c0;
        #pragma unroll
        for (int j = 0; j < 8; ++j) {
            float4 v = *(const float4*)(p + j * 4);
            acc[j].x += v.x; acc[j].y += v.y; acc[j].z += v.z; acc[j].w += v.w;
        }
    }
    float* orow = out + ((size_t)b * TT + g * 128 + r) * HH + c0;
    #pragma unroll
    for (int j = 0; j < 8; ++j) {
        float4 v = make_float4(acc[j].x * inv, acc[j].y * inv, acc[j].z * inv, acc[j].w * inv);
        *(float4*)(orow + j * 4) = v;
    }
}

// ---------------------------------------------------------------------------
extern "C" void kernel_launch(void* const* d_in, const int* in_sizes, int n_in,
                              void* d_out, int out_size)
{
    (void)in_sizes; (void)n_in; (void)out_size;
    const float* x  = (const float*)d_in[0];
    const float* Wq = (const float*)d_in[1];
    const float* Wk = (const float*)d_in[2];
    const float* Wv = (const float*)d_in[3];
    float* out = (float*)d_out;

    cudaFuncSetAttribute(proj_mma, cudaFuncAttributeMaxDynamicSharedMemorySize, PROJ_SMEM);
    cudaFuncSetAttribute(flash_chunk, cudaFuncAttributeMaxDynamicSharedMemorySize, FLASH_SMEM);

    conv_x<<<8192, 256>>>(x);
    conv_w<<<48, 256>>>(Wq, Wk, Wv);
    proj_mma<<<(BB * TT) / 128, 256, PROJ_SMEM>>>(0);
    flash_chunk<<<dim3(NCHUNK, BB), 256, FLASH_SMEM>>>(0);
    combine_kernel<<<dim3(32, BB), 256>>>(out);
}

// round 8
// speedup vs baseline: 8.5602x; 1.1167x over previous
#include <cuda_runtime.h>
#include <cuda_fp16.h>
#include <cstdint>

#define BB 8
#define TT 4096
#define DD 512
#define HH 64

// device-global scratch (allocation-free)
__device__ __half g_qh[BB * TT * HH];            // [b*T + t][h]
__device__ __half g_kh[BB * TT * HH];            // [b*T + t][h]
__device__ __half g_vt[BB * HH * TT];            // [b][h][t]  (V transposed)
__device__ __half g_w3h[DD * 192];               // fp16 W interleaved [k][m*64+n]
#define NCHUNK 144                               // key-chunks per batch
__device__ float g_po[BB * NCHUNK * 128 * 64];   // partial O (unnormalized)
__device__ float g_pl[BB * NCHUNK * 128];        // partial l

__device__ __forceinline__ uint32_t smem_to_u32(const void* p) {
    uint32_t a;
    asm("{ .reg .u64 t; cvta.to.shared.u64 t, %1; cvt.u32.u64 %0, t; }" : "=r"(a) : "l"(p));
    return a;
}
#define CP_ASYNC16(dst, src) \
    asm volatile("cp.async.cg.shared.global [%0], [%1], 16;" :: "r"(dst), "l"(src))
#define CP_COMMIT() asm volatile("cp.async.commit_group;")
#define CP_WAIT0()  asm volatile("cp.async.wait_group 0;" ::: "memory")

#define MMA_F16(d, a, b0, b1) \
    asm volatile("mma.sync.aligned.m16n8k16.row.col.f32.f16.f16.f32 " \
        "{%0,%1,%2,%3}, {%4,%5,%6,%7}, {%8,%9}, {%0,%1,%2,%3};" \
        : "+f"((d)[0]), "+f"((d)[1]), "+f"((d)[2]), "+f"((d)[3]) \
        : "r"((a)[0]), "r"((a)[1]), "r"((a)[2]), "r"((a)[3]), "r"(b0), "r"(b1))

// ---------------------------------------------------------------------------
// W pre-conversion: fp32 -> fp16, interleaved [k][m*64+n]
// ---------------------------------------------------------------------------
__global__ __launch_bounds__(256) void conv_w(
    const float* __restrict__ Wq, const float* __restrict__ Wk, const float* __restrict__ Wv)
{
    int gid = blockIdx.x * 256 + threadIdx.x;      // 12288 threads, 8 halves each
    int col = (gid * 8) % 192;
    int k   = (gid * 8) / 192;
    int m   = col / 64;
    int n   = col % 64;
    const float* W = (m == 0) ? Wq : ((m == 1) ? Wk : Wv);
    float4 a = *(const float4*)&W[(size_t)k * HH + n];
    float4 b = *(const float4*)&W[(size_t)k * HH + n + 4];
    __half2 h0 = __floats2half2_rn(a.x, a.y);
    __half2 h1 = __floats2half2_rn(a.z, a.w);
    __half2 h2 = __floats2half2_rn(b.x, b.y);
    __half2 h3 = __floats2half2_rn(b.z, b.w);
    uint4 o;
    o.x = *(uint32_t*)&h0; o.y = *(uint32_t*)&h1;
    o.z = *(uint32_t*)&h2; o.w = *(uint32_t*)&h3;
    *(uint4*)&g_w3h[(size_t)k * 192 + col] = o;
}

// ---------------------------------------------------------------------------
// Kernel 1: QKV projection. 64-row CTA tiles, fp32 X loaded direct via LDG
// register prefetch (cvt->STS), W fp16 cp.async double-buffered.
// ---------------------------------------------------------------------------
#define XP 72    // X tile pitch (halves)
#define WP 200   // W tile pitch (halves)
#define VP 72    // V staging pitch (halves)
#define PX0 0
#define PX1 9216
#define PW0 18432
#define PW1 44032
#define PROJ_SMEM 69632

__device__ __forceinline__ void w_cp(uint32_t smb, int kc, int buf, int tid)
{
    const __half* wsrc = g_w3h + (size_t)(kc * 64) * 192;
    const uint32_t wb = smb + (buf ? PW1 : PW0);
    #pragma unroll
    for (int it = 0; it < 6; ++it) {
        int idx = tid + it * 256;                  // 0..1535
        int r = idx / 24, c = idx % 24;
        CP_ASYNC16(wb + (uint32_t)(r * (WP * 2) + c * 16), wsrc + (size_t)r * 192 + c * 8);
    }
}

__global__ __launch_bounds__(256, 2) void proj_mma(const float* __restrict__ x)
{
    extern __shared__ __align__(16) char psm[];
    const uint32_t smb = smem_to_u32(psm);
    __half* Vst = (__half*)psm;                    // reuses X buffers after mainloop

    const int tid  = threadIdx.x;
    const int warp = tid >> 5;
    const int lane = tid & 31;
    const int wm   = warp >> 2;                    // 0..1 (32 rows each)
    const int wn   = warp & 3;                     // 0..3 (48 cols each)
    const int row0 = blockIdx.x * 64;

    float acc[2][6][4];
    #pragma unroll
    for (int mt = 0; mt < 2; ++mt)
        #pragma unroll
        for (int nt = 0; nt < 6; ++nt)
            acc[mt][nt][0] = acc[mt][nt][1] = acc[mt][nt][2] = acc[mt][nt][3] = 0.f;

    float4 xr[4];
    // thread's 4 float4 slots: idx = tid + it*256, r = idx>>4, c4 = (idx&15)*4
    #pragma unroll
    for (int it = 0; it < 4; ++it) {
        int idx = tid + it * 256;
        int r = idx >> 4, c4 = (idx & 15) * 4;
        xr[it] = *(const float4*)&x[(size_t)(row0 + r) * DD + 0 * 64 + c4];
    }
    // STS kc=0 into buf0
    {
        __half* Xb = (__half*)(psm + PX0);
        #pragma unroll
        for (int it = 0; it < 4; ++it) {
            int idx = tid + it * 256;
            int r = idx >> 4, c4 = (idx & 15) * 4;
            __half2 h0 = __floats2half2_rn(xr[it].x, xr[it].y);
            __half2 h1 = __floats2half2_rn(xr[it].z, xr[it].w);
            uint2 pk; pk.x = *(uint32_t*)&h0; pk.y = *(uint32_t*)&h1;
            *(uint2*)&Xb[r * XP + c4] = pk;
        }
    }
    w_cp(smb, 0, 0, tid);
    CP_COMMIT();
    // prefetch kc=1 X into regs
    #pragma unroll
    for (int it = 0; it < 4; ++it) {
        int idx = tid + it * 256;
        int r = idx >> 4, c4 = (idx & 15) * 4;
        xr[it] = *(const float4*)&x[(size_t)(row0 + r) * DD + 1 * 64 + c4];
    }
    CP_WAIT0();
    __syncthreads();

    for (int kc = 0; kc < 8; ++kc) {
        if (kc < 7) { w_cp(smb, kc + 1, (kc + 1) & 1, tid); CP_COMMIT(); }

        const uint32_t xb = smb + ((kc & 1) ? PX1 : PX0);
        const uint32_t wb = smb + ((kc & 1) ? PW1 : PW0);

        #pragma unroll
        for (int ks = 0; ks < 4; ++ks) {
            uint32_t a[2][4];
            #pragma unroll
            for (int mt = 0; mt < 2; ++mt) {
                int row = wm * 32 + mt * 16 + (lane & 7) + ((lane >> 3) & 1) * 8;
                int col = ks * 16 + ((lane >> 4) << 3);
                uint32_t ad = xb + (uint32_t)(row * XP + col) * 2;
                asm volatile("ldmatrix.sync.aligned.m8n8.x4.shared.b16 {%0,%1,%2,%3}, [%4];"
                    : "=r"(a[mt][0]), "=r"(a[mt][1]), "=r"(a[mt][2]), "=r"(a[mt][3])
                    : "r"(ad));
            }
            #pragma unroll
            for (int nt = 0; nt < 6; ++nt) {
                uint32_t b0, b1;
                uint32_t ad = wb +
                    (uint32_t)((ks * 16 + (lane & 15)) * WP + wn * 48 + nt * 8) * 2;
                asm volatile("ldmatrix.sync.aligned.m8n8.x2.trans.shared.b16 {%0,%1}, [%2];"
                    : "=r"(b0), "=r"(b1) : "r"(ad));
                #pragma unroll
                for (int mt = 0; mt < 2; ++mt)
                    MMA_F16(acc[mt][nt], a[mt], b0, b1);
            }
        }

        if (kc < 7) {
            // STS prefetched X into the other buffer
            __half* Xb = (__half*)(psm + (((kc + 1) & 1) ? PX1 : PX0));
            #pragma unroll
            for (int it = 0; it < 4; ++it) {
                int idx = tid + it * 256;
                int r = idx >> 4, c4 = (idx & 15) * 4;
                __half2 h0 = __floats2half2_rn(xr[it].x, xr[it].y);
                __half2 h1 = __floats2half2_rn(xr[it].z, xr[it].w);
                uint2 pk; pk.x = *(uint32_t*)&h0; pk.y = *(uint32_t*)&h1;
                *(uint2*)&Xb[r * XP + c4] = pk;
            }
            if (kc < 6) {
                #pragma unroll
                for (int it = 0; it < 4; ++it) {
                    int idx = tid + it * 256;
                    int r = idx >> 4, c4 = (idx & 15) * 4;
                    xr[it] = *(const float4*)&x[(size_t)(row0 + r) * DD + (kc + 2) * 64 + c4];
                }
            }
            CP_WAIT0();
        }
        __syncthreads();
    }

    // ---- store Q/K direct; stage V for transposed coalesced write ----
    const int rA = lane >> 2;
    const int cA = (lane & 3) * 2;
    #pragma unroll
    for (int mt = 0; mt < 2; ++mt) {
        #pragma unroll
        for (int nt = 0; nt < 6; ++nt) {
            const int n0 = wn * 48 + nt * 8 + cA;
            const int r  = wm * 32 + mt * 16 + rA;
            if (n0 < 128) {
                __half* dst = (n0 < 64) ? g_qh : g_kh;
                const int nn = n0 & 63;
                *(__half2*)&dst[(size_t)(row0 + r) * HH + nn] =
                    __floats2half2_rn(acc[mt][nt][0], acc[mt][nt][1]);
                *(__half2*)&dst[(size_t)(row0 + r + 8) * HH + nn] =
                    __floats2half2_rn(acc[mt][nt][2], acc[mt][nt][3]);
            } else {
                const int h = n0 - 128;
                Vst[h * VP + r]           = __float2half(acc[mt][nt][0]);
                Vst[(h + 1) * VP + r]     = __float2half(acc[mt][nt][1]);
                Vst[h * VP + r + 8]       = __float2half(acc[mt][nt][2]);
                Vst[(h + 1) * VP + r + 8] = __float2half(acc[mt][nt][3]);
            }
        }
    }
    __syncthreads();

    const int b  = row0 >> 12;
    const int t0 = row0 & (TT - 1);
    #pragma unroll
    for (int it = 0; it < 2; ++it) {
        int idx = tid + it * 256;                  // 0..511
        int h = idx >> 3, tc = (idx & 7) * 8;
        uint4 v = *(uint4*)&Vst[h * VP + tc];
        *(uint4*)&g_vt[((size_t)b * HH + h) * TT + t0 + tc] = v;
    }
}

// ---------------------------------------------------------------------------
// Kernel 2: split-K flash chunks. Item = (b, qblock g, key-chunk c of <=8 tiles)
// exp computed in f16x2 on MUFU (halves the MUFU load vs f32 ex2).
// ---------------------------------------------------------------------------
#define PITCH 72
#define QOFF  0
#define KOFF0 18432
#define KOFF1 27648
#define VOFF0 36864
#define VOFF1 46080
#define FLASH_SMEM 55296

__device__ __forceinline__ void kv_cp(uint32_t smb, const __half* kg, const __half* vtg,
                                      int j0, int buf, int tid)
{
    const uint32_t kb = smb + (buf ? KOFF1 : KOFF0);
    const uint32_t vb = smb + (buf ? VOFF1 : VOFF0);
    #pragma unroll
    for (int it = 0; it < 2; ++it) {
        int idx = tid + it * 256;
        int r = idx >> 3, c = idx & 7;
        CP_ASYNC16(kb + (uint32_t)(r * (PITCH * 2) + c * 16),
                   kg + (size_t)(j0 + r) * HH + c * 8);
        CP_ASYNC16(vb + (uint32_t)(r * (PITCH * 2) + c * 16),
                   vtg + (size_t)r * TT + j0 + c * 8);
    }
}

__global__ __launch_bounds__(256, 2) void flash_chunk(int dummy)
{
    extern __shared__ __align__(16) char sm[];
    const uint32_t smb = smem_to_u32(sm);

    const int tid  = threadIdx.x;
    const int warp = tid >> 5;
    const int lane = tid & 31;
    const int b    = blockIdx.y;

    // decode work item -> (g, c)
    int g = 0, cch = 0;
    {
        int it = blockIdx.x, off = 0;
        #pragma unroll 1
        for (int gg = 0; gg < 32; ++gg) {
            int cg = (2 * gg + 9) >> 3;
            if (it < off + cg) { g = gg; cch = it - off; break; }
            off += cg;
        }
    }
    const int qi0 = g * 128;
    const int t0  = cch * 8;
    const int t1  = min(t0 + 8, 2 * g + 2);

    const __half* qg  = g_qh + ((size_t)b * TT + qi0) * HH;
    const __half* kg  = g_kh + (size_t)b * TT * HH;
    const __half* vtg = g_vt + (size_t)b * HH * TT;

    // prologue: Q + first K/V tile
    #pragma unroll
    for (int it = 0; it < 4; ++it) {
        int idx = tid + it * 256;
        int r = idx >> 3, c = idx & 7;
        CP_ASYNC16(smb + QOFF + (uint32_t)(r * (PITCH * 2) + c * 16),
                   qg + (size_t)r * HH + c * 8);
    }
    kv_cp(smb, kg, vtg, t0 * 64, t0 & 1, tid);
    CP_COMMIT();
    CP_WAIT0();
    __syncthreads();

    // Q A-fragments
    const int mrow = warp * 16;
    uint32_t aq[4][4];
    {
        int row = mrow + (lane & 7) + ((lane >> 3) & 1) * 8;
        int col = ((lane >> 4) << 3);
        #pragma unroll
        for (int ks = 0; ks < 4; ++ks) {
            uint32_t ad = smb + QOFF + (uint32_t)(row * PITCH + ks * 16 + col) * 2;
            asm volatile("ldmatrix.sync.aligned.m8n8.x4.shared.b16 {%0,%1,%2,%3}, [%4];"
                : "=r"(aq[ks][0]), "=r"(aq[ks][1]), "=r"(aq[ks][2]), "=r"(aq[ks][3])
                : "r"(ad));
        }
    }

    const int lr0 = mrow + (lane >> 2);           // local rows
    const int lr1 = lr0 + 8;
    const int r0g = qi0 + lr0;                    // global rows (for mask)
    const int r1g = r0g + 8;
    const int cql = (lane & 3) * 2;

    float o[8][4];
    #pragma unroll
    for (int n = 0; n < 8; ++n)
        #pragma unroll
        for (int i = 0; i < 4; ++i) o[n][i] = 0.f;
    float l0 = 0.f, l1 = 0.f;

    const int b4r = ((lane >> 4) << 3) + (lane & 7);
    const int b4c = ((lane >> 3) & 1) * 8;
    const float SC = 0.044194173824159216f * 1.4426950408889634f;

    for (int t = t0; t < t1; ++t) {
        if (t + 1 < t1) { kv_cp(smb, kg, vtg, (t + 1) * 64, (t + 1) & 1, tid); CP_COMMIT(); }

        const uint32_t kbase = smb + ((t & 1) ? KOFF1 : KOFF0);
        const uint32_t vbase = smb + ((t & 1) ? VOFF1 : VOFF0);
        const int j0 = t * 64;

        // ---- S = Q K^T (x4 B loads: 2 j-tiles per ldmatrix) ----
        float s[8][4];
        #pragma unroll
        for (int n = 0; n < 8; n += 2) {
            s[n][0] = s[n][1] = s[n][2] = s[n][3] = 0.f;
            s[n+1][0] = s[n+1][1] = s[n+1][2] = s[n+1][3] = 0.f;
            #pragma unroll
            for (int ks = 0; ks < 4; ++ks) {
                uint32_t b0, b1, b2, b3;
                uint32_t ad = kbase + (uint32_t)((n * 8 + b4r) * PITCH + ks * 16 + b4c) * 2;
                asm volatile("ldmatrix.sync.aligned.m8n8.x4.shared.b16 {%0,%1,%2,%3}, [%4];"
                    : "=r"(b0), "=r"(b1), "=r"(b2), "=r"(b3) : "r"(ad));
                MMA_F16(s[n],     aq[ks], b0, b1);
                MMA_F16(s[n + 1], aq[ks], b2, b3);
            }
        }

        // ---- exp in f16x2 (+ mask only on diagonal tiles); P lands packed ----
        uint32_t pl[8], pr[8];
        #pragma unroll
        for (int n = 0; n < 8; ++n) {
            float a0 = s[n][0] * SC;
            float a1 = s[n][1] * SC;
            float a2 = s[n][2] * SC;
            float a3 = s[n][3] * SC;
            if (t >= 2 * g) {
                const int cb = j0 + n * 8 + cql;
                if (cb     > r0g) a0 = -60000.f;
                if (cb + 1 > r0g) a1 = -60000.f;
                if (cb     > r1g) a2 = -60000.f;
                if (cb + 1 > r1g) a3 = -60000.f;
            }
            uint32_t i0, i1;
            asm("cvt.rn.f16x2.f32 %0, %1, %2;" : "=r"(i0) : "f"(a1), "f"(a0));
            asm("cvt.rn.f16x2.f32 %0, %1, %2;" : "=r"(i1) : "f"(a3), "f"(a2));
            asm("ex2.approx.f16x2 %0, %1;" : "=r"(pl[n]) : "r"(i0));
            asm("ex2.approx.f16x2 %0, %1;" : "=r"(pr[n]) : "r"(i1));
            float2 f0 = __half22float2(*(const __half2*)&pl[n]);
            float2 f1 = __half22float2(*(const __half2*)&pr[n]);
            l0 += f0.x + f0.y;
            l1 += f1.x + f1.y;
        }

        // ---- O += P V (x4 B loads: 2 h-tiles per ldmatrix) ----
        #pragma unroll
        for (int hn = 0; hn < 8; hn += 2) {
            #pragma unroll
            for (int kk = 0; kk < 4; ++kk) {
                uint32_t b0, b1, b2, b3;
                uint32_t ad = vbase + (uint32_t)((hn * 8 + b4r) * PITCH + kk * 16 + b4c) * 2;
                asm volatile("ldmatrix.sync.aligned.m8n8.x4.shared.b16 {%0,%1,%2,%3}, [%4];"
                    : "=r"(b0), "=r"(b1), "=r"(b2), "=r"(b3) : "r"(ad));
                uint32_t ap[4] = {pl[2*kk], pr[2*kk], pl[2*kk+1], pr[2*kk+1]};
                MMA_F16(o[hn],     ap, b0, b1);
                MMA_F16(o[hn + 1], ap, b2, b3);
            }
        }

        if (t + 1 < t1) CP_WAIT0();
        __syncthreads();
    }

    // ---- epilogue: quad-reduce l, store unnormalized partials ----
    l0 += __shfl_xor_sync(0xffffffffu, l0, 1);
    l0 += __shfl_xor_sync(0xffffffffu, l0, 2);
    l1 += __shfl_xor_sync(0xffffffffu, l1, 1);
    l1 += __shfl_xor_sync(0xffffffffu, l1, 2);

    const int item = b * NCHUNK + (int)blockIdx.x;
    if ((lane & 3) == 0) {
        g_pl[(size_t)item * 128 + lr0] = l0;
        g_pl[(size_t)item * 128 + lr1] = l1;
    }
    float* po = g_po + (size_t)item * (128 * 64);
    float* p0 = po + lr0 * 64 + cql;
    float* p1 = po + lr1 * 64 + cql;
    #pragma unroll
    for (int hn = 0; hn < 8; ++hn) {
        *(float2*)(p0 + hn * 8) = make_float2(o[hn][0], o[hn][1]);
        *(float2*)(p1 + hn * 8) = make_float2(o[hn][2], o[hn][3]);
    }
}

// ---------------------------------------------------------------------------
// Kernel 3: combine partials and normalize
// ---------------------------------------------------------------------------
__global__ __launch_bounds__(256) void combine_kernel(float* __restrict__ out)
{
    const int g = blockIdx.x, b = blockIdx.y;
    int off = 0;
    #pragma unroll 1
    for (int gg = 0; gg < 32; ++gg) { if (gg < g) off += (2 * gg + 9) >> 3; }
    const int nc   = (2 * g + 9) >> 3;
    const int base = b * NCHUNK + off;

    const int tid = threadIdx.x;
    const int r   = tid >> 1;
    const int c0  = (tid & 1) * 32;

    float l = 0.f;
    #pragma unroll 1
    for (int c = 0; c < nc; ++c) l += g_pl[(size_t)(base + c) * 128 + r];
    const float inv = 1.0f / l;

    float4 acc[8];
    #pragma unroll
    for (int j = 0; j < 8; ++j) acc[j] = make_float4(0.f, 0.f, 0.f, 0.f);
    #pragma unroll 1
    for (int c = 0; c < nc; ++c) {
        const float* p = g_po + (size_t)(base + c) * (128 * 64) + r * 64 + c0;
        #pragma unroll
        for (int j = 0; j < 8; ++j) {
            float4 v = *(const float4*)(p + j * 4);
            acc[j].x += v.x; acc[j].y += v.y; acc[j].z += v.z; acc[j].w += v.w;
        }
    }
    float* orow = out + ((size_t)b * TT + g * 128 + r) * HH + c0;
    #pragma unroll
    for (int j = 0; j < 8; ++j) {
        float4 v = make_float4(acc[j].x * inv, acc[j].y * inv, acc[j].z * inv, acc[j].w * inv);
        *(float4*)(orow + j * 4) = v;
    }
}

// ---------------------------------------------------------------------------
extern "C" void kernel_launch(void* const* d_in, const int* in_sizes, int n_in,
                              void* d_out, int out_size)
{
    (void)in_sizes; (void)n_in; (void)out_size;
    const float* x  = (const float*)d_in[0];
    const float* Wq = (const float*)d_in[1];
    const float* Wk = (const float*)d_in[2];
    const float* Wv = (const float*)d_in[3];
    float* out = (float*)d_out;

    cudaFuncSetAttribute(proj_mma, cudaFuncAttributeMaxDynamicSharedMemorySize, PROJ_SMEM);
    cudaFuncSetAttribute(flash_chunk, cudaFuncAttributeMaxDynamicSharedMemorySize, FLASH_SMEM);

    conv_w<<<48, 256>>>(Wq, Wk, Wv);
    proj_mma<<<(BB * TT) / 64, 256, PROJ_SMEM>>>(x);
    flash_chunk<<<dim3(NCHUNK, BB), 256, FLASH_SMEM>>>(0);
    combine_kernel<<<dim3(32, BB), 256>>>(out);
}

// round 9
// speedup vs baseline: 9.6212x; 1.1239x over previous
#include <cuda_runtime.h>
#include <cuda_fp16.h>
#include <cstdint>

#define BB 8
#define TT 4096
#define DD 512
#define HH 64

// device-global scratch (allocation-free)
__device__ __half g_qh[BB * TT * HH];            // [b*T + t][h]
__device__ __half g_kh[BB * TT * HH];            // [b*T + t][h]
__device__ __half g_vt[BB * HH * TT];            // [b][h][t]  (V transposed)
__device__ __half g_w3h[DD * 192];               // fp16 W interleaved [k][m*64+n]
#define NCHUNK 144                               // key-chunks per batch
__device__ __half g_po[BB * NCHUNK * 128 * 64];  // partial O (unnormalized, fp16)
__device__ float  g_pl[BB * NCHUNK * 128];       // partial l

__device__ __forceinline__ uint32_t smem_to_u32(const void* p) {
    uint32_t a;
    asm("{ .reg .u64 t; cvta.to.shared.u64 t, %1; cvt.u32.u64 %0, t; }" : "=r"(a) : "l"(p));
    return a;
}
#define CP_ASYNC16(dst, src) \
    asm volatile("cp.async.cg.shared.global [%0], [%1], 16;" :: "r"(dst), "l"(src))
#define CP_COMMIT() asm volatile("cp.async.commit_group;")
#define CP_WAIT0()  asm volatile("cp.async.wait_group 0;" ::: "memory")

#define MMA_F16(d, a, b0, b1) \
    asm volatile("mma.sync.aligned.m16n8k16.row.col.f32.f16.f16.f32 " \
        "{%0,%1,%2,%3}, {%4,%5,%6,%7}, {%8,%9}, {%0,%1,%2,%3};" \
        : "+f"((d)[0]), "+f"((d)[1]), "+f"((d)[2]), "+f"((d)[3]) \
        : "r"((a)[0]), "r"((a)[1]), "r"((a)[2]), "r"((a)[3]), "r"(b0), "r"(b1))

// ---------------------------------------------------------------------------
// W pre-conversion: fp32 -> fp16, interleaved [k][m*64+n]
// ---------------------------------------------------------------------------
__global__ __launch_bounds__(256) void conv_w(
    const float* __restrict__ Wq, const float* __restrict__ Wk, const float* __restrict__ Wv)
{
    int gid = blockIdx.x * 256 + threadIdx.x;      // 12288 threads, 8 halves each
    int col = (gid * 8) % 192;
    int k   = (gid * 8) / 192;
    int m   = col / 64;
    int n   = col % 64;
    const float* W = (m == 0) ? Wq : ((m == 1) ? Wk : Wv);
    float4 a = *(const float4*)&W[(size_t)k * HH + n];
    float4 b = *(const float4*)&W[(size_t)k * HH + n + 4];
    __half2 h0 = __floats2half2_rn(a.x, a.y);
    __half2 h1 = __floats2half2_rn(a.z, a.w);
    __half2 h2 = __floats2half2_rn(b.x, b.y);
    __half2 h3 = __floats2half2_rn(b.z, b.w);
    uint4 o;
    o.x = *(uint32_t*)&h0; o.y = *(uint32_t*)&h1;
    o.z = *(uint32_t*)&h2; o.w = *(uint32_t*)&h3;
    *(uint4*)&g_w3h[(size_t)k * 192 + col] = o;
}

// ---------------------------------------------------------------------------
// Kernel 1: QKV projection. 64-row CTA tiles, fp32 X loaded direct via LDG
// register prefetch (cvt->STS), W fp16 cp.async double-buffered.
// ---------------------------------------------------------------------------
#define XP 72    // X tile pitch (halves)
#define WP 200   // W tile pitch (halves)
#define VP 72    // V staging pitch (halves)
#define PX0 0
#define PX1 9216
#define PW0 18432
#define PW1 44032
#define PROJ_SMEM 69632

__device__ __forceinline__ void w_cp(uint32_t smb, int kc, int buf, int tid)
{
    const __half* wsrc = g_w3h + (size_t)(kc * 64) * 192;
    const uint32_t wb = smb + (buf ? PW1 : PW0);
    #pragma unroll
    for (int it = 0; it < 6; ++it) {
        int idx = tid + it * 256;                  // 0..1535
        int r = idx / 24, c = idx % 24;
        CP_ASYNC16(wb + (uint32_t)(r * (WP * 2) + c * 16), wsrc + (size_t)r * 192 + c * 8);
    }
}

__global__ __launch_bounds__(256, 2) void proj_mma(const float* __restrict__ x)
{
    extern __shared__ __align__(16) char psm[];
    const uint32_t smb = smem_to_u32(psm);
    __half* Vst = (__half*)psm;                    // reuses X buffers after mainloop

    const int tid  = threadIdx.x;
    const int warp = tid >> 5;
    const int lane = tid & 31;
    const int wm   = warp >> 2;                    // 0..1 (32 rows each)
    const int wn   = warp & 3;                     // 0..3 (48 cols each)
    const int row0 = blockIdx.x * 64;

    float acc[2][6][4];
    #pragma unroll
    for (int mt = 0; mt < 2; ++mt)
        #pragma unroll
        for (int nt = 0; nt < 6; ++nt)
            acc[mt][nt][0] = acc[mt][nt][1] = acc[mt][nt][2] = acc[mt][nt][3] = 0.f;

    float4 xr[4];
    #pragma unroll
    for (int it = 0; it < 4; ++it) {
        int idx = tid + it * 256;
        int r = idx >> 4, c4 = (idx & 15) * 4;
        xr[it] = *(const float4*)&x[(size_t)(row0 + r) * DD + 0 * 64 + c4];
    }
    {
        __half* Xb = (__half*)(psm + PX0);
        #pragma unroll
        for (int it = 0; it < 4; ++it) {
            int idx = tid + it * 256;
            int r = idx >> 4, c4 = (idx & 15) * 4;
            __half2 h0 = __floats2half2_rn(xr[it].x, xr[it].y);
            __half2 h1 = __floats2half2_rn(xr[it].z, xr[it].w);
            uint2 pk; pk.x = *(uint32_t*)&h0; pk.y = *(uint32_t*)&h1;
            *(uint2*)&Xb[r * XP + c4] = pk;
        }
    }
    w_cp(smb, 0, 0, tid);
    CP_COMMIT();
    #pragma unroll
    for (int it = 0; it < 4; ++it) {
        int idx = tid + it * 256;
        int r = idx >> 4, c4 = (idx & 15) * 4;
        xr[it] = *(const float4*)&x[(size_t)(row0 + r) * DD + 1 * 64 + c4];
    }
    CP_WAIT0();
    __syncthreads();

    for (int kc = 0; kc < 8; ++kc) {
        if (kc < 7) { w_cp(smb, kc + 1, (kc + 1) & 1, tid); CP_COMMIT(); }

        const uint32_t xb = smb + ((kc & 1) ? PX1 : PX0);
        const uint32_t wb = smb + ((kc & 1) ? PW1 : PW0);

        #pragma unroll
        for (int ks = 0; ks < 4; ++ks) {
            uint32_t a[2][4];
            #pragma unroll
            for (int mt = 0; mt < 2; ++mt) {
                int row = wm * 32 + mt * 16 + (lane & 7) + ((lane >> 3) & 1) * 8;
                int col = ks * 16 + ((lane >> 4) << 3);
                uint32_t ad = xb + (uint32_t)(row * XP + col) * 2;
                asm volatile("ldmatrix.sync.aligned.m8n8.x4.shared.b16 {%0,%1,%2,%3}, [%4];"
                    : "=r"(a[mt][0]), "=r"(a[mt][1]), "=r"(a[mt][2]), "=r"(a[mt][3])
                    : "r"(ad));
            }
            #pragma unroll
            for (int nt = 0; nt < 6; ++nt) {
                uint32_t b0, b1;
                uint32_t ad = wb +
                    (uint32_t)((ks * 16 + (lane & 15)) * WP + wn * 48 + nt * 8) * 2;
                asm volatile("ldmatrix.sync.aligned.m8n8.x2.trans.shared.b16 {%0,%1}, [%2];"
                    : "=r"(b0), "=r"(b1) : "r"(ad));
                #pragma unroll
                for (int mt = 0; mt < 2; ++mt)
                    MMA_F16(acc[mt][nt], a[mt], b0, b1);
            }
        }

        if (kc < 7) {
            __half* Xb = (__half*)(psm + (((kc + 1) & 1) ? PX1 : PX0));
            #pragma unroll
            for (int it = 0; it < 4; ++it) {
                int idx = tid + it * 256;
                int r = idx >> 4, c4 = (idx & 15) * 4;
                __half2 h0 = __floats2half2_rn(xr[it].x, xr[it].y);
                __half2 h1 = __floats2half2_rn(xr[it].z, xr[it].w);
                uint2 pk; pk.x = *(uint32_t*)&h0; pk.y = *(uint32_t*)&h1;
                *(uint2*)&Xb[r * XP + c4] = pk;
            }
            if (kc < 6) {
                #pragma unroll
                for (int it = 0; it < 4; ++it) {
                    int idx = tid + it * 256;
                    int r = idx >> 4, c4 = (idx & 15) * 4;
                    xr[it] = *(const float4*)&x[(size_t)(row0 + r) * DD + (kc + 2) * 64 + c4];
                }
            }
            CP_WAIT0();
        }
        __syncthreads();
    }

    // ---- store Q/K direct; stage V for transposed coalesced write ----
    const int rA = lane >> 2;
    const int cA = (lane & 3) * 2;
    #pragma unroll
    for (int mt = 0; mt < 2; ++mt) {
        #pragma unroll
        for (int nt = 0; nt < 6; ++nt) {
            const int n0 = wn * 48 + nt * 8 + cA;
            const int r  = wm * 32 + mt * 16 + rA;
            if (n0 < 128) {
                __half* dst = (n0 < 64) ? g_qh : g_kh;
                const int nn = n0 & 63;
                *(__half2*)&dst[(size_t)(row0 + r) * HH + nn] =
                    __floats2half2_rn(acc[mt][nt][0], acc[mt][nt][1]);
                *(__half2*)&dst[(size_t)(row0 + r + 8) * HH + nn] =
                    __floats2half2_rn(acc[mt][nt][2], acc[mt][nt][3]);
            } else {
                const int h = n0 - 128;
                Vst[h * VP + r]           = __float2half(acc[mt][nt][0]);
                Vst[(h + 1) * VP + r]     = __float2half(acc[mt][nt][1]);
                Vst[h * VP + r + 8]       = __float2half(acc[mt][nt][2]);
                Vst[(h + 1) * VP + r + 8] = __float2half(acc[mt][nt][3]);
            }
        }
    }
    __syncthreads();

    const int b  = row0 >> 12;
    const int t0 = row0 & (TT - 1);
    #pragma unroll
    for (int it = 0; it < 2; ++it) {
        int idx = tid + it * 256;                  // 0..511
        int h = idx >> 3, tc = (idx & 7) * 8;
        uint4 v = *(uint4*)&Vst[h * VP + tc];
        *(uint4*)&g_vt[((size_t)b * HH + h) * TT + t0 + tc] = v;
    }
}

// ---------------------------------------------------------------------------
// Kernel 2: split-K flash chunks. Item = (b, qblock g, key-chunk c of <=8 tiles)
// exp computed in f16x2 on MUFU; partial O stored fp16.
// ---------------------------------------------------------------------------
#define PITCH 72
#define QOFF  0
#define KOFF0 18432
#define KOFF1 27648
#define VOFF0 36864
#define VOFF1 46080
#define FLASH_SMEM 55296

__device__ __forceinline__ void kv_cp(uint32_t smb, const __half* kg, const __half* vtg,
                                      int j0, int buf, int tid)
{
    const uint32_t kb = smb + (buf ? KOFF1 : KOFF0);
    const uint32_t vb = smb + (buf ? VOFF1 : VOFF0);
    #pragma unroll
    for (int it = 0; it < 2; ++it) {
        int idx = tid + it * 256;
        int r = idx >> 3, c = idx & 7;
        CP_ASYNC16(kb + (uint32_t)(r * (PITCH * 2) + c * 16),
                   kg + (size_t)(j0 + r) * HH + c * 8);
        CP_ASYNC16(vb + (uint32_t)(r * (PITCH * 2) + c * 16),
                   vtg + (size_t)r * TT + j0 + c * 8);
    }
}

__global__ __launch_bounds__(256, 2) void flash_chunk(int dummy)
{
    extern __shared__ __align__(16) char sm[];
    const uint32_t smb = smem_to_u32(sm);

    const int tid  = threadIdx.x;
    const int warp = tid >> 5;
    const int lane = tid & 31;
    const int b    = blockIdx.y;

    // decode work item -> (g, c)
    int g = 0, cch = 0;
    {
        int it = blockIdx.x, off = 0;
        #pragma unroll 1
        for (int gg = 0; gg < 32; ++gg) {
            int cg = (2 * gg + 9) >> 3;
            if (it < off + cg) { g = gg; cch = it - off; break; }
            off += cg;
        }
    }
    const int qi0 = g * 128;
    const int t0  = cch * 8;
    const int t1  = min(t0 + 8, 2 * g + 2);

    const __half* qg  = g_qh + ((size_t)b * TT + qi0) * HH;
    const __half* kg  = g_kh + (size_t)b * TT * HH;
    const __half* vtg = g_vt + (size_t)b * HH * TT;

    // prologue: Q + first K/V tile
    #pragma unroll
    for (int it = 0; it < 4; ++it) {
        int idx = tid + it * 256;
        int r = idx >> 3, c = idx & 7;
        CP_ASYNC16(smb + QOFF + (uint32_t)(r * (PITCH * 2) + c * 16),
                   qg + (size_t)r * HH + c * 8);
    }
    kv_cp(smb, kg, vtg, t0 * 64, t0 & 1, tid);
    CP_COMMIT();
    CP_WAIT0();
    __syncthreads();

    // Q A-fragments
    const int mrow = warp * 16;
    uint32_t aq[4][4];
    {
        int row = mrow + (lane & 7) + ((lane >> 3) & 1) * 8;
        int col = ((lane >> 4) << 3);
        #pragma unroll
        for (int ks = 0; ks < 4; ++ks) {
            uint32_t ad = smb + QOFF + (uint32_t)(row * PITCH + ks * 16 + col) * 2;
            asm volatile("ldmatrix.sync.aligned.m8n8.x4.shared.b16 {%0,%1,%2,%3}, [%4];"
                : "=r"(aq[ks][0]), "=r"(aq[ks][1]), "=r"(aq[ks][2]), "=r"(aq[ks][3])
                : "r"(ad));
        }
    }

    const int lr0 = mrow + (lane >> 2);           // local rows
    const int lr1 = lr0 + 8;
    const int r0g = qi0 + lr0;                    // global rows (for mask)
    const int r1g = r0g + 8;
    const int cql = (lane & 3) * 2;

    float o[8][4];
    #pragma unroll
    for (int n = 0; n < 8; ++n)
        #pragma unroll
        for (int i = 0; i < 4; ++i) o[n][i] = 0.f;
    float l0 = 0.f, l1 = 0.f;

    const int b4r = ((lane >> 4) << 3) + (lane & 7);
    const int b4c = ((lane >> 3) & 1) * 8;
    const float SC = 0.044194173824159216f * 1.4426950408889634f;

    for (int t = t0; t < t1; ++t) {
        if (t + 1 < t1) { kv_cp(smb, kg, vtg, (t + 1) * 64, (t + 1) & 1, tid); CP_COMMIT(); }

        const uint32_t kbase = smb + ((t & 1) ? KOFF1 : KOFF0);
        const uint32_t vbase = smb + ((t & 1) ? VOFF1 : VOFF0);
        const int j0 = t * 64;

        // ---- S = Q K^T (x4 B loads: 2 j-tiles per ldmatrix) ----
        float s[8][4];
        #pragma unroll
        for (int n = 0; n < 8; n += 2) {
            s[n][0] = s[n][1] = s[n][2] = s[n][3] = 0.f;
            s[n+1][0] = s[n+1][1] = s[n+1][2] = s[n+1][3] = 0.f;
            #pragma unroll
            for (int ks = 0; ks < 4; ++ks) {
                uint32_t b0, b1, b2, b3;
                uint32_t ad = kbase + (uint32_t)((n * 8 + b4r) * PITCH + ks * 16 + b4c) * 2;
                asm volatile("ldmatrix.sync.aligned.m8n8.x4.shared.b16 {%0,%1,%2,%3}, [%4];"
                    : "=r"(b0), "=r"(b1), "=r"(b2), "=r"(b3) : "r"(ad));
                MMA_F16(s[n],     aq[ks], b0, b1);
                MMA_F16(s[n + 1], aq[ks], b2, b3);
            }
        }

        // ---- exp in f16x2 (+ mask only on diagonal tiles); P lands packed ----
        uint32_t pl[8], pr[8];
        #pragma unroll
        for (int n = 0; n < 8; ++n) {
            float a0 = s[n][0] * SC;
            float a1 = s[n][1] * SC;
            float a2 = s[n][2] * SC;
            float a3 = s[n][3] * SC;
            if (t >= 2 * g) {
                const int cb = j0 + n * 8 + cql;
                if (cb     > r0g) a0 = -60000.f;
                if (cb + 1 > r0g) a1 = -60000.f;
                if (cb     > r1g) a2 = -60000.f;
                if (cb + 1 > r1g) a3 = -60000.f;
            }
            uint32_t i0, i1;
            asm("cvt.rn.f16x2.f32 %0, %1, %2;" : "=r"(i0) : "f"(a1), "f"(a0));
            asm("cvt.rn.f16x2.f32 %0, %1, %2;" : "=r"(i1) : "f"(a3), "f"(a2));
            asm("ex2.approx.f16x2 %0, %1;" : "=r"(pl[n]) : "r"(i0));
            asm("ex2.approx.f16x2 %0, %1;" : "=r"(pr[n]) : "r"(i1));
            float2 f0 = __half22float2(*(const __half2*)&pl[n]);
            float2 f1 = __half22float2(*(const __half2*)&pr[n]);
            l0 += f0.x + f0.y;
            l1 += f1.x + f1.y;
        }

        // ---- O += P V (x4 B loads: 2 h-tiles per ldmatrix) ----
        #pragma unroll
        for (int hn = 0; hn < 8; hn += 2) {
            #pragma unroll
            for (int kk = 0; kk < 4; ++kk) {
                uint32_t b0, b1, b2, b3;
                uint32_t ad = vbase + (uint32_t)((hn * 8 + b4r) * PITCH + kk * 16 + b4c) * 2;
                asm volatile("ldmatrix.sync.aligned.m8n8.x4.shared.b16 {%0,%1,%2,%3}, [%4];"
                    : "=r"(b0), "=r"(b1), "=r"(b2), "=r"(b3) : "r"(ad));
                uint32_t ap[4] = {pl[2*kk], pr[2*kk], pl[2*kk+1], pr[2*kk+1]};
                MMA_F16(o[hn],     ap, b0, b1);
                MMA_F16(o[hn + 1], ap, b2, b3);
            }
        }

        if (t + 1 < t1) CP_WAIT0();
        __syncthreads();
    }

    // ---- epilogue: quad-reduce l, store unnormalized fp16 partials ----
    l0 += __shfl_xor_sync(0xffffffffu, l0, 1);
    l0 += __shfl_xor_sync(0xffffffffu, l0, 2);
    l1 += __shfl_xor_sync(0xffffffffu, l1, 1);
    l1 += __shfl_xor_sync(0xffffffffu, l1, 2);

    const int item = b * NCHUNK + (int)blockIdx.x;
    if ((lane & 3) == 0) {
        g_pl[(size_t)item * 128 + lr0] = l0;
        g_pl[(size_t)item * 128 + lr1] = l1;
    }
    __half* po = g_po + (size_t)item * (128 * 64);
    __half* p0 = po + lr0 * 64 + cql;
    __half* p1 = po + lr1 * 64 + cql;
    #pragma unroll
    for (int hn = 0; hn < 8; ++hn) {
        *(__half2*)(p0 + hn * 8) = __floats2half2_rn(o[hn][0], o[hn][1]);
        *(__half2*)(p1 + hn * 8) = __floats2half2_rn(o[hn][2], o[hn][3]);
    }
}

// ---------------------------------------------------------------------------
// Kernel 3: combine fp16 partials and normalize. CTA owns 32 q-rows.
// grid: (128, BB)  with  g = bx>>2, row-chunk = bx&3.
// ---------------------------------------------------------------------------
__global__ __launch_bounds__(256) void combine_kernel(float* __restrict__ out)
{
    const int bx = blockIdx.x;
    const int g  = bx >> 2;
    const int rc = bx & 3;
    const int b  = blockIdx.y;

    int off = 0;
    #pragma unroll 1
    for (int gg = 0; gg < 32; ++gg) { if (gg < g) off += (2 * gg + 9) >> 3; }
    const int nc   = (2 * g + 9) >> 3;
    const int base = b * NCHUNK + off;

    const int tid = threadIdx.x;
    const int r   = rc * 32 + (tid >> 3);          // q row within the 128-block
    const int c0  = (tid & 7) * 8;                 // 8 halves per thread

    float l = 0.f;
    #pragma unroll 1
    for (int c = 0; c < nc; ++c) l += g_pl[(size_t)(base + c) * 128 + r];
    const float inv = 1.0f / l;

    float acc[8];
    #pragma unroll
    for (int j = 0; j < 8; ++j) acc[j] = 0.f;
    #pragma unroll 1
    for (int c = 0; c < nc; ++c) {
        const __half* p = g_po + (size_t)(base + c) * (128 * 64) + r * 64 + c0;
        uint4 v = *(const uint4*)p;
        float2 f0 = __half22float2(*(const __half2*)&v.x);
        float2 f1 = __half22float2(*(const __half2*)&v.y);
        float2 f2 = __half22float2(*(const __half2*)&v.z);
        float2 f3 = __half22float2(*(const __half2*)&v.w);
        acc[0] += f0.x; acc[1] += f0.y;
        acc[2] += f1.x; acc[3] += f1.y;
        acc[4] += f2.x; acc[5] += f2.y;
        acc[6] += f3.x; acc[7] += f3.y;
    }
    float* orow = out + ((size_t)b * TT + g * 128 + r) * HH + c0;
    float4 w0 = make_float4(acc[0] * inv, acc[1] * inv, acc[2] * inv, acc[3] * inv);
    float4 w1 = make_float4(acc[4] * inv, acc[5] * inv, acc[6] * inv, acc[7] * inv);
    *(float4*)(orow)     = w0;
    *(float4*)(orow + 4) = w1;
}

// ---------------------------------------------------------------------------
extern "C" void kernel_launch(void* const* d_in, const int* in_sizes, int n_in,
                              void* d_out, int out_size)
{
    (void)in_sizes; (void)n_in; (void)out_size;
    const float* x  = (const float*)d_in[0];
    const float* Wq = (const float*)d_in[1];
    const float* Wk = (const float*)d_in[2];
    const float* Wv = (const float*)d_in[3];
    float* out = (float*)d_out;

    cudaFuncSetAttribute(proj_mma, cudaFuncAttributeMaxDynamicSharedMemorySize, PROJ_SMEM);
    cudaFuncSetAttribute(flash_chunk, cudaFuncAttributeMaxDynamicSharedMemorySize, FLASH_SMEM);

    conv_w<<<48, 256>>>(Wq, Wk, Wv);
    proj_mma<<<(BB * TT) / 64, 256, PROJ_SMEM>>>(x);
    flash_chunk<<<dim3(NCHUNK, BB), 256, FLASH_SMEM>>>(0);
    combine_kernel<<<dim3(128, BB), 256>>>(out);
}

// round 10
// speedup vs baseline: 10.0866x; 1.0484x over previous
#include <cuda_runtime.h>
#include <cuda_fp16.h>
#include <cstdint>

#define BB 8
#define TT 4096
#define DD 512
#define HH 64

// device-global scratch (allocation-free)
__device__ __half g_qh[BB * TT * HH];            // [b*T + t][h]
__device__ __half g_kh[BB * TT * HH];            // [b*T + t][h]
__device__ __half g_vt[BB * HH * TT];            // [b][h][t]  (V transposed)
__device__ __half g_w3h[DD * 192];               // fp16 W interleaved [k][m*64+n]
#define NCHUNK 144                               // key-chunks per batch
__device__ __half g_po[BB * NCHUNK * 128 * 64];  // partial O (unnormalized, fp16)
__device__ float  g_pl[BB * NCHUNK * 128];       // partial l

__device__ __forceinline__ uint32_t smem_to_u32(const void* p) {
    uint32_t a;
    asm("{ .reg .u64 t; cvta.to.shared.u64 t, %1; cvt.u32.u64 %0, t; }" : "=r"(a) : "l"(p));
    return a;
}
#define CP_ASYNC16(dst, src) \
    asm volatile("cp.async.cg.shared.global [%0], [%1], 16;" :: "r"(dst), "l"(src))
#define CP_COMMIT() asm volatile("cp.async.commit_group;")
#define CP_WAIT0()  asm volatile("cp.async.wait_group 0;" ::: "memory")

#define MMA_F16(d, a, b0, b1) \
    asm volatile("mma.sync.aligned.m16n8k16.row.col.f32.f16.f16.f32 " \
        "{%0,%1,%2,%3}, {%4,%5,%6,%7}, {%8,%9}, {%0,%1,%2,%3};" \
        : "+f"((d)[0]), "+f"((d)[1]), "+f"((d)[2]), "+f"((d)[3]) \
        : "r"((a)[0]), "r"((a)[1]), "r"((a)[2]), "r"((a)[3]), "r"(b0), "r"(b1))

// ---------------------------------------------------------------------------
// W pre-conversion: fp32 -> fp16, interleaved [k][m*64+n]
// ---------------------------------------------------------------------------
__global__ __launch_bounds__(256) void conv_w(
    const float* __restrict__ Wq, const float* __restrict__ Wk, const float* __restrict__ Wv)
{
    int gid = blockIdx.x * 256 + threadIdx.x;      // 12288 threads, 8 halves each
    int col = (gid * 8) % 192;
    int k   = (gid * 8) / 192;
    int m   = col / 64;
    int n   = col % 64;
    const float* W = (m == 0) ? Wq : ((m == 1) ? Wk : Wv);
    float4 a = *(const float4*)&W[(size_t)k * HH + n];
    float4 b = *(const float4*)&W[(size_t)k * HH + n + 4];
    __half2 h0 = __floats2half2_rn(a.x, a.y);
    __half2 h1 = __floats2half2_rn(a.z, a.w);
    __half2 h2 = __floats2half2_rn(b.x, b.y);
    __half2 h3 = __floats2half2_rn(b.z, b.w);
    uint4 o;
    o.x = *(uint32_t*)&h0; o.y = *(uint32_t*)&h1;
    o.z = *(uint32_t*)&h2; o.w = *(uint32_t*)&h3;
    *(uint4*)&g_w3h[(size_t)k * 192 + col] = o;
}

// ---------------------------------------------------------------------------
// Kernel 1: QKV projection. 64-row CTA tiles, fp32 X loaded direct via LDG
// register prefetch (cvt->STS), W fp16 cp.async double-buffered.
// ---------------------------------------------------------------------------
#define XP 72    // X tile pitch (halves)
#define WP 200   // W tile pitch (halves)
#define VP 72    // V staging pitch (halves)
#define PX0 0
#define PX1 9216
#define PW0 18432
#define PW1 44032
#define PROJ_SMEM 69632

__device__ __forceinline__ void w_cp(uint32_t smb, int kc, int buf, int tid)
{
    const __half* wsrc = g_w3h + (size_t)(kc * 64) * 192;
    const uint32_t wb = smb + (buf ? PW1 : PW0);
    #pragma unroll
    for (int it = 0; it < 6; ++it) {
        int idx = tid + it * 256;                  // 0..1535
        int r = idx / 24, c = idx % 24;
        CP_ASYNC16(wb + (uint32_t)(r * (WP * 2) + c * 16), wsrc + (size_t)r * 192 + c * 8);
    }
}

__global__ __launch_bounds__(256, 2) void proj_mma(const float* __restrict__ x)
{
    extern __shared__ __align__(16) char psm[];
    const uint32_t smb = smem_to_u32(psm);
    __half* Vst = (__half*)psm;                    // reuses X buffers after mainloop

    const int tid  = threadIdx.x;
    const int warp = tid >> 5;
    const int lane = tid & 31;
    const int wm   = warp >> 2;                    // 0..1 (32 rows each)
    const int wn   = warp & 3;                     // 0..3 (48 cols each)
    const int row0 = blockIdx.x * 64;

    float acc[2][6][4];
    #pragma unroll
    for (int mt = 0; mt < 2; ++mt)
        #pragma unroll
        for (int nt = 0; nt < 6; ++nt)
            acc[mt][nt][0] = acc[mt][nt][1] = acc[mt][nt][2] = acc[mt][nt][3] = 0.f;

    float4 xr[4];
    #pragma unroll
    for (int it = 0; it < 4; ++it) {
        int idx = tid + it * 256;
        int r = idx >> 4, c4 = (idx & 15) * 4;
        xr[it] = *(const float4*)&x[(size_t)(row0 + r) * DD + 0 * 64 + c4];
    }
    {
        __half* Xb = (__half*)(psm + PX0);
        #pragma unroll
        for (int it = 0; it < 4; ++it) {
            int idx = tid + it * 256;
            int r = idx >> 4, c4 = (idx & 15) * 4;
            __half2 h0 = __floats2half2_rn(xr[it].x, xr[it].y);
            __half2 h1 = __floats2half2_rn(xr[it].z, xr[it].w);
            uint2 pk; pk.x = *(uint32_t*)&h0; pk.y = *(uint32_t*)&h1;
            *(uint2*)&Xb[r * XP + c4] = pk;
        }
    }
    w_cp(smb, 0, 0, tid);
    CP_COMMIT();
    #pragma unroll
    for (int it = 0; it < 4; ++it) {
        int idx = tid + it * 256;
        int r = idx >> 4, c4 = (idx & 15) * 4;
        xr[it] = *(const float4*)&x[(size_t)(row0 + r) * DD + 1 * 64 + c4];
    }
    CP_WAIT0();
    __syncthreads();

    for (int kc = 0; kc < 8; ++kc) {
        if (kc < 7) { w_cp(smb, kc + 1, (kc + 1) & 1, tid); CP_COMMIT(); }

        const uint32_t xb = smb + ((kc & 1) ? PX1 : PX0);
        const uint32_t wb = smb + ((kc & 1) ? PW1 : PW0);

        #pragma unroll
        for (int ks = 0; ks < 4; ++ks) {
            uint32_t a[2][4];
            #pragma unroll
            for (int mt = 0; mt < 2; ++mt) {
                int row = wm * 32 + mt * 16 + (lane & 7) + ((lane >> 3) & 1) * 8;
                int col = ks * 16 + ((lane >> 4) << 3);
                uint32_t ad = xb + (uint32_t)(row * XP + col) * 2;
                asm volatile("ldmatrix.sync.aligned.m8n8.x4.shared.b16 {%0,%1,%2,%3}, [%4];"
                    : "=r"(a[mt][0]), "=r"(a[mt][1]), "=r"(a[mt][2]), "=r"(a[mt][3])
                    : "r"(ad));
            }
            #pragma unroll
            for (int nt = 0; nt < 6; ++nt) {
                uint32_t b0, b1;
                uint32_t ad = wb +
                    (uint32_t)((ks * 16 + (lane & 15)) * WP + wn * 48 + nt * 8) * 2;
                asm volatile("ldmatrix.sync.aligned.m8n8.x2.trans.shared.b16 {%0,%1}, [%2];"
                    : "=r"(b0), "=r"(b1) : "r"(ad));
                #pragma unroll
                for (int mt = 0; mt < 2; ++mt)
                    MMA_F16(acc[mt][nt], a[mt], b0, b1);
            }
        }

        if (kc < 7) {
            __half* Xb = (__half*)(psm + (((kc + 1) & 1) ? PX1 : PX0));
            #pragma unroll
            for (int it = 0; it < 4; ++it) {
                int idx = tid + it * 256;
                int r = idx >> 4, c4 = (idx & 15) * 4;
                __half2 h0 = __floats2half2_rn(xr[it].x, xr[it].y);
                __half2 h1 = __floats2half2_rn(xr[it].z, xr[it].w);
                uint2 pk; pk.x = *(uint32_t*)&h0; pk.y = *(uint32_t*)&h1;
                *(uint2*)&Xb[r * XP + c4] = pk;
            }
            if (kc < 6) {
                #pragma unroll
                for (int it = 0; it < 4; ++it) {
                    int idx = tid + it * 256;
                    int r = idx >> 4, c4 = (idx & 15) * 4;
                    xr[it] = *(const float4*)&x[(size_t)(row0 + r) * DD + (kc + 2) * 64 + c4];
                }
            }
            CP_WAIT0();
        }
        __syncthreads();
    }

    // ---- store Q/K direct; stage V for transposed coalesced write ----
    const int rA = lane >> 2;
    const int cA = (lane & 3) * 2;
    #pragma unroll
    for (int mt = 0; mt < 2; ++mt) {
        #pragma unroll
        for (int nt = 0; nt < 6; ++nt) {
            const int n0 = wn * 48 + nt * 8 + cA;
            const int r  = wm * 32 + mt * 16 + rA;
            if (n0 < 128) {
                __half* dst = (n0 < 64) ? g_qh : g_kh;
                const int nn = n0 & 63;
                *(__half2*)&dst[(size_t)(row0 + r) * HH + nn] =
                    __floats2half2_rn(acc[mt][nt][0], acc[mt][nt][1]);
                *(__half2*)&dst[(size_t)(row0 + r + 8) * HH + nn] =
                    __floats2half2_rn(acc[mt][nt][2], acc[mt][nt][3]);
            } else {
                const int h = n0 - 128;
                Vst[h * VP + r]           = __float2half(acc[mt][nt][0]);
                Vst[(h + 1) * VP + r]     = __float2half(acc[mt][nt][1]);
                Vst[h * VP + r + 8]       = __float2half(acc[mt][nt][2]);
                Vst[(h + 1) * VP + r + 8] = __float2half(acc[mt][nt][3]);
            }
        }
    }
    __syncthreads();

    const int b  = row0 >> 12;
    const int t0 = row0 & (TT - 1);
    #pragma unroll
    for (int it = 0; it < 2; ++it) {
        int idx = tid + it * 256;                  // 0..511
        int h = idx >> 3, tc = (idx & 7) * 8;
        uint4 v = *(uint4*)&Vst[h * VP + tc];
        *(uint4*)&g_vt[((size_t)b * HH + h) * TT + t0 + tc] = v;
    }
}

// ---------------------------------------------------------------------------
// Kernel 2: split-K flash chunks. Item = (b, qblock g, key-chunk c of <=8 tiles)
// exp in f16x2 on MUFU; l computed on the tensor pipe via P x ones-vector MMA.
// ---------------------------------------------------------------------------
#define PITCH 72
#define QOFF  0
#define KOFF0 18432
#define KOFF1 27648
#define VOFF0 36864
#define VOFF1 46080
#define FLASH_SMEM 55296

__device__ __forceinline__ void kv_cp(uint32_t smb, const __half* kg, const __half* vtg,
                                      int j0, int buf, int tid)
{
    const uint32_t kb = smb + (buf ? KOFF1 : KOFF0);
    const uint32_t vb = smb + (buf ? VOFF1 : VOFF0);
    #pragma unroll
    for (int it = 0; it < 2; ++it) {
        int idx = tid + it * 256;
        int r = idx >> 3, c = idx & 7;
        CP_ASYNC16(kb + (uint32_t)(r * (PITCH * 2) + c * 16),
                   kg + (size_t)(j0 + r) * HH + c * 8);
        CP_ASYNC16(vb + (uint32_t)(r * (PITCH * 2) + c * 16),
                   vtg + (size_t)r * TT + j0 + c * 8);
    }
}

__global__ __launch_bounds__(256, 2) void flash_chunk(int dummy)
{
    extern __shared__ __align__(16) char sm[];
    const uint32_t smb = smem_to_u32(sm);

    const int tid  = threadIdx.x;
    const int warp = tid >> 5;
    const int lane = tid & 31;
    const int b    = blockIdx.y;

    // decode work item -> (g, c)
    int g = 0, cch = 0;
    {
        int it = blockIdx.x, off = 0;
        #pragma unroll 1
        for (int gg = 0; gg < 32; ++gg) {
            int cg = (2 * gg + 9) >> 3;
            if (it < off + cg) { g = gg; cch = it - off; break; }
            off += cg;
        }
    }
    const int qi0 = g * 128;
    const int t0  = cch * 8;
    const int t1  = min(t0 + 8, 2 * g + 2);

    const __half* qg  = g_qh + ((size_t)b * TT + qi0) * HH;
    const __half* kg  = g_kh + (size_t)b * TT * HH;
    const __half* vtg = g_vt + (size_t)b * HH * TT;

    // prologue: Q + first K/V tile
    #pragma unroll
    for (int it = 0; it < 4; ++it) {
        int idx = tid + it * 256;
        int r = idx >> 3, c = idx & 7;
        CP_ASYNC16(smb + QOFF + (uint32_t)(r * (PITCH * 2) + c * 16),
                   qg + (size_t)r * HH + c * 8);
    }
    kv_cp(smb, kg, vtg, t0 * 64, t0 & 1, tid);
    CP_COMMIT();
    CP_WAIT0();
    __syncthreads();

    // Q A-fragments
    const int mrow = warp * 16;
    uint32_t aq[4][4];
    {
        int row = mrow + (lane & 7) + ((lane >> 3) & 1) * 8;
        int col = ((lane >> 4) << 3);
        #pragma unroll
        for (int ks = 0; ks < 4; ++ks) {
            uint32_t ad = smb + QOFF + (uint32_t)(row * PITCH + ks * 16 + col) * 2;
            asm volatile("ldmatrix.sync.aligned.m8n8.x4.shared.b16 {%0,%1,%2,%3}, [%4];"
                : "=r"(aq[ks][0]), "=r"(aq[ks][1]), "=r"(aq[ks][2]), "=r"(aq[ks][3])
                : "r"(ad));
        }
    }

    const int lr0 = mrow + (lane >> 2);           // local rows
    const int lr1 = lr0 + 8;
    const int r0g = qi0 + lr0;                    // global rows (for mask)
    const int r1g = r0g + 8;
    const int cql = (lane & 3) * 2;

    float o[8][4];
    #pragma unroll
    for (int n = 0; n < 8; ++n)
        #pragma unroll
        for (int i = 0; i < 4; ++i) o[n][i] = 0.f;
    float lacc[4] = {0.f, 0.f, 0.f, 0.f};         // l via P x ones MMA
    const uint32_t ONE2 = 0x3C003C00u;            // half2(1.0, 1.0)

    const int b4r = ((lane >> 4) << 3) + (lane & 7);
    const int b4c = ((lane >> 3) & 1) * 8;
    const float SC = 0.044194173824159216f * 1.4426950408889634f;

    for (int t = t0; t < t1; ++t) {
        if (t + 1 < t1) { kv_cp(smb, kg, vtg, (t + 1) * 64, (t + 1) & 1, tid); CP_COMMIT(); }

        const uint32_t kbase = smb + ((t & 1) ? KOFF1 : KOFF0);
        const uint32_t vbase = smb + ((t & 1) ? VOFF1 : VOFF0);
        const int j0 = t * 64;

        // ---- S = Q K^T (x4 B loads: 2 j-tiles per ldmatrix) ----
        float s[8][4];
        #pragma unroll
        for (int n = 0; n < 8; n += 2) {
            s[n][0] = s[n][1] = s[n][2] = s[n][3] = 0.f;
            s[n+1][0] = s[n+1][1] = s[n+1][2] = s[n+1][3] = 0.f;
            #pragma unroll
            for (int ks = 0; ks < 4; ++ks) {
                uint32_t b0, b1, b2, b3;
                uint32_t ad = kbase + (uint32_t)((n * 8 + b4r) * PITCH + ks * 16 + b4c) * 2;
                asm volatile("ldmatrix.sync.aligned.m8n8.x4.shared.b16 {%0,%1,%2,%3}, [%4];"
                    : "=r"(b0), "=r"(b1), "=r"(b2), "=r"(b3) : "r"(ad));
                MMA_F16(s[n],     aq[ks], b0, b1);
                MMA_F16(s[n + 1], aq[ks], b2, b3);
            }
        }

        // ---- exp in f16x2 (+ mask only on diagonal tiles); P lands packed ----
        uint32_t pl[8], pr[8];
        #pragma unroll
        for (int n = 0; n < 8; ++n) {
            float a0 = s[n][0] * SC;
            float a1 = s[n][1] * SC;
            float a2 = s[n][2] * SC;
            float a3 = s[n][3] * SC;
            if (t >= 2 * g) {
                const int cb = j0 + n * 8 + cql;
                if (cb     > r0g) a0 = -60000.f;
                if (cb + 1 > r0g) a1 = -60000.f;
                if (cb     > r1g) a2 = -60000.f;
                if (cb + 1 > r1g) a3 = -60000.f;
            }
            uint32_t i0, i1;
            asm("cvt.rn.f16x2.f32 %0, %1, %2;" : "=r"(i0) : "f"(a1), "f"(a0));
            asm("cvt.rn.f16x2.f32 %0, %1, %2;" : "=r"(i1) : "f"(a3), "f"(a2));
            asm("ex2.approx.f16x2 %0, %1;" : "=r"(pl[n]) : "r"(i0));
            asm("ex2.approx.f16x2 %0, %1;" : "=r"(pr[n]) : "r"(i1));
        }

        // ---- l += P x ones (tensor pipe), then O += P V ----
        #pragma unroll
        for (int kk = 0; kk < 4; ++kk) {
            uint32_t ap[4] = {pl[2*kk], pr[2*kk], pl[2*kk+1], pr[2*kk+1]};
            MMA_F16(lacc, ap, ONE2, ONE2);
        }
        #pragma unroll
        for (int hn = 0; hn < 8; hn += 2) {
            #pragma unroll
            for (int kk = 0; kk < 4; ++kk) {
                uint32_t b0, b1, b2, b3;
                uint32_t ad = vbase + (uint32_t)((hn * 8 + b4r) * PITCH + kk * 16 + b4c) * 2;
                asm volatile("ldmatrix.sync.aligned.m8n8.x4.shared.b16 {%0,%1,%2,%3}, [%4];"
                    : "=r"(b0), "=r"(b1), "=r"(b2), "=r"(b3) : "r"(ad));
                uint32_t ap[4] = {pl[2*kk], pr[2*kk], pl[2*kk+1], pr[2*kk+1]};
                MMA_F16(o[hn],     ap, b0, b1);
                MMA_F16(o[hn + 1], ap, b2, b3);
            }
        }

        if (t + 1 < t1) CP_WAIT0();
        __syncthreads();
    }

    // ---- epilogue: l already reduced by the ones-MMA; store fp16 partials ----
    const int item = b * NCHUNK + (int)blockIdx.x;
    if ((lane & 3) == 0) {
        g_pl[(size_t)item * 128 + lr0] = lacc[0];
        g_pl[(size_t)item * 128 + lr1] = lacc[2];
    }
    __half* po = g_po + (size_t)item * (128 * 64);
    __half* p0 = po + lr0 * 64 + cql;
    __half* p1 = po + lr1 * 64 + cql;
    #pragma unroll
    for (int hn = 0; hn < 8; ++hn) {
        *(__half2*)(p0 + hn * 8) = __floats2half2_rn(o[hn][0], o[hn][1]);
        *(__half2*)(p1 + hn * 8) = __floats2half2_rn(o[hn][2], o[hn][3]);
    }
}

// ---------------------------------------------------------------------------
// Kernel 3: combine fp16 partials and normalize. CTA owns 32 q-rows.
// Prefetched predicated loads: MLP ~ nc instead of 1.
// ---------------------------------------------------------------------------
__global__ __launch_bounds__(256) void combine_kernel(float* __restrict__ out)
{
    const int bx = blockIdx.x;
    const int g  = bx >> 2;
    const int rc = bx & 3;
    const int b  = blockIdx.y;

    int off = 0;
    #pragma unroll 1
    for (int gg = 0; gg < 32; ++gg) { if (gg < g) off += (2 * gg + 9) >> 3; }
    const int nc   = (2 * g + 9) >> 3;
    const int base = b * NCHUNK + off;

    const int tid = threadIdx.x;
    const int r   = rc * 32 + (tid >> 3);          // q row within the 128-block
    const int c0  = (tid & 7) * 8;                 // 8 halves per thread

    // prefetch all chunk data with independent loads
    float lv[9];
    uint4 pv[9];
    #pragma unroll
    for (int c = 0; c < 9; ++c) {
        if (c < nc) {
            lv[c] = g_pl[(size_t)(base + c) * 128 + r];
            pv[c] = *(const uint4*)(g_po + (size_t)(base + c) * (128 * 64) + r * 64 + c0);
        }
    }

    float l = 0.f;
    float acc[8];
    #pragma unroll
    for (int j = 0; j < 8; ++j) acc[j] = 0.f;
    #pragma unroll
    for (int c = 0; c < 9; ++c) {
        if (c < nc) {
            l += lv[c];
            float2 f0 = __half22float2(*(const __half2*)&pv[c].x);
            float2 f1 = __half22float2(*(const __half2*)&pv[c].y);
            float2 f2 = __half22float2(*(const __half2*)&pv[c].z);
            float2 f3 = __half22float2(*(const __half2*)&pv[c].w);
            acc[0] += f0.x; acc[1] += f0.y;
            acc[2] += f1.x; acc[3] += f1.y;
            acc[4] += f2.x; acc[5] += f2.y;
            acc[6] += f3.x; acc[7] += f3.y;
        }
    }
    const float inv = 1.0f / l;
    float* orow = out + ((size_t)b * TT + g * 128 + r) * HH + c0;
    float4 w0 = make_float4(acc[0] * inv, acc[1] * inv, acc[2] * inv, acc[3] * inv);
    float4 w1 = make_float4(acc[4] * inv, acc[5] * inv, acc[6] * inv, acc[7] * inv);
    *(float4*)(orow)     = w0;
    *(float4*)(orow + 4) = w1;
}

// ---------------------------------------------------------------------------
extern "C" void kernel_launch(void* const* d_in, const int* in_sizes, int n_in,
                              void* d_out, int out_size)
{
    (void)in_sizes; (void)n_in; (void)out_size;
    const float* x  = (const float*)d_in[0];
    const float* Wq = (const float*)d_in[1];
    const float* Wk = (const float*)d_in[2];
    const float* Wv = (const float*)d_in[3];
    float* out = (float*)d_out;

    cudaFuncSetAttribute(proj_mma, cudaFuncAttributeMaxDynamicSharedMemorySize, PROJ_SMEM);
    cudaFuncSetAttribute(flash_chunk, cudaFuncAttributeMaxDynamicSharedMemorySize, FLASH_SMEM);

    conv_w<<<48, 256>>>(Wq, Wk, Wv);
    proj_mma<<<(BB * TT) / 64, 256, PROJ_SMEM>>>(x);
    flash_chunk<<<dim3(NCHUNK, BB), 256, FLASH_SMEM>>>(0);
    combine_kernel<<<dim3(128, BB), 256>>>(out);
}